// round 1
// baseline (speedup 1.0000x reference)
#include <cuda_runtime.h>

#define NB     4
#define C      256
#define L      4096
#define GROUPS 32
#define CPG    8      // channels per group
#define HEADS  4
#define DH     64
#define EPS    1e-5f

// ---------------- scratch (no allocation allowed) ----------------
__device__ float g_xn[(size_t)NB * C * L];            // group-normed x, [n][c][l]
__device__ float g_q [(size_t)NB * HEADS * L * DH];   // [n][h][l][d]
__device__ float g_k [(size_t)NB * HEADS * L * DH];
__device__ float g_v [(size_t)NB * HEADS * L * DH];
__device__ float g_ao[(size_t)NB * C * L];            // attention out, [n][c][l]

// ---------------- GroupNorm ----------------
// one block per (n, group): reduce 8*4096 = 32768 contiguous floats
__global__ __launch_bounds__(256) void gn_kernel(const float* __restrict__ x,
                                                 const float* __restrict__ gamma,
                                                 const float* __restrict__ beta,
                                                 float* __restrict__ xn) {
    int n = blockIdx.x >> 5, g = blockIdx.x & 31;
    size_t base = ((size_t)n * C + g * CPG) * L;
    const float4* xp = (const float4*)(x + base);
    float s = 0.f, ss = 0.f;
    const int NV = CPG * L / 4;  // 8192 float4s
    for (int i = threadIdx.x; i < NV; i += 256) {
        float4 v = xp[i];
        s  += v.x + v.y + v.z + v.w;
        ss += v.x*v.x + v.y*v.y + v.z*v.z + v.w*v.w;
    }
    __shared__ float rs[256], rq[256];
    rs[threadIdx.x] = s; rq[threadIdx.x] = ss;
    __syncthreads();
    for (int off = 128; off; off >>= 1) {
        if (threadIdx.x < off) {
            rs[threadIdx.x] += rs[threadIdx.x + off];
            rq[threadIdx.x] += rq[threadIdx.x + off];
        }
        __syncthreads();
    }
    float mean = rs[0] * (1.f / (CPG * L));
    float var  = rq[0] * (1.f / (CPG * L)) - mean * mean;
    float inv  = rsqrtf(var + EPS);
    float4* op = (float4*)(xn + base);
    for (int i = threadIdx.x; i < NV; i += 256) {
        int c = g * CPG + (i >> 10);   // L/4 = 1024 float4s per channel
        float gm = gamma[c] * inv;
        float bt = beta[c] - mean * gm;
        float4 v = xp[i];
        float4 o;
        o.x = v.x * gm + bt; o.y = v.y * gm + bt;
        o.z = v.z * gm + bt; o.w = v.w * gm + bt;
        op[i] = o;
    }
}

// ---------------- 1x1-conv GEMM: out[o,l] = sum_c W[o,c] * X[c,l] ----------------
// grid (L/64, C/64, N), block (16,16), 64x64 tile, 4x4 microtile, BK=16
// mode 0: write head-split [n][h][l][d] ; mode 1: write [n][c][l] + bias
__global__ __launch_bounds__(256) void proj_kernel(const float* __restrict__ Wm,
                                                   const float* __restrict__ X,
                                                   float* __restrict__ out,
                                                   const float* __restrict__ bias,
                                                   int mode) {
    __shared__ float Ws[16][64];  // [k][o_local]
    __shared__ float Xs[16][64];  // [k][l_local]
    int n = blockIdx.z;
    int obase = blockIdx.y * 64;
    int lbase = blockIdx.x * 64;
    const float* Xn = X + (size_t)n * C * L;
    int tid = threadIdx.y * 16 + threadIdx.x;
    float acc[4][4] = {};
    for (int kb = 0; kb < C; kb += 16) {
        {   // W tile: 64x16, transposed into smem
            int ol = tid >> 2, k4 = (tid & 3) * 4;
            float4 w = *(const float4*)&Wm[(size_t)(obase + ol) * C + kb + k4];
            Ws[k4 + 0][ol] = w.x; Ws[k4 + 1][ol] = w.y;
            Ws[k4 + 2][ol] = w.z; Ws[k4 + 3][ol] = w.w;
        }
        {   // X tile: 16x64
            int cl = tid >> 4, l4 = (tid & 15) * 4;
            *(float4*)&Xs[cl][l4] =
                *(const float4*)&Xn[(size_t)(kb + cl) * L + lbase + l4];
        }
        __syncthreads();
#pragma unroll
        for (int k = 0; k < 16; ++k) {
            float4 a = *(const float4*)&Ws[k][threadIdx.y * 4];
            float4 b = *(const float4*)&Xs[k][threadIdx.x * 4];
            acc[0][0] += a.x*b.x; acc[0][1] += a.x*b.y; acc[0][2] += a.x*b.z; acc[0][3] += a.x*b.w;
            acc[1][0] += a.y*b.x; acc[1][1] += a.y*b.y; acc[1][2] += a.y*b.z; acc[1][3] += a.y*b.w;
            acc[2][0] += a.z*b.x; acc[2][1] += a.z*b.y; acc[2][2] += a.z*b.z; acc[2][3] += a.z*b.w;
            acc[3][0] += a.w*b.x; acc[3][1] += a.w*b.y; acc[3][2] += a.w*b.z; acc[3][3] += a.w*b.w;
        }
        __syncthreads();
    }
    if (mode == 0) {
        // 64-row tiles align with heads: h = obase/64, d = local row
        int h = obase >> 6;
        float* outp = out + ((size_t)(n * HEADS + h)) * L * DH;
#pragma unroll
        for (int i = 0; i < 4; ++i) {
            int d = threadIdx.y * 4 + i;
#pragma unroll
            for (int j = 0; j < 4; ++j) {
                int l = lbase + threadIdx.x * 4 + j;
                outp[(size_t)l * DH + d] = acc[i][j];
            }
        }
    } else {
#pragma unroll
        for (int i = 0; i < 4; ++i) {
            int o = obase + threadIdx.y * 4 + i;
            float bv = bias[o];
#pragma unroll
            for (int j = 0; j < 4; ++j) {
                out[((size_t)n * C + o) * L + lbase + threadIdx.x * 4 + j] = acc[i][j] + bv;
            }
        }
    }
}

// ---------------- flash attention (fp32) ----------------
// grid (L/64, N*HEADS), block 256 (logical 16x16); 64 q-rows per block
#define ATTN_SMEM_FLOATS (3 * 4096 + 64 * 65 + 3 * 64)
__global__ __launch_bounds__(256) void attn_kernel(const float* __restrict__ Q,
                                                   const float* __restrict__ K,
                                                   const float* __restrict__ V,
                                                   float* __restrict__ AO) {
    extern __shared__ float sm[];
    float* Qs = sm;                 // [d][r]   4096
    float* Ks = Qs + 4096;          // [d][c]   4096
    float* Vs = Ks + 4096;          // [m][d]   4096
    float* Ss = Vs + 4096;          // [r][m]   pitch 65
    float* mrow = Ss + 64 * 65;
    float* lrow = mrow + 64;
    float* srow = lrow + 64;

    int tid = threadIdx.x;
    int tx = tid & 15, ty = tid >> 4;
    int qb = blockIdx.x, nh = blockIdx.y;
    int n = nh >> 2, h = nh & 3;
    const float* Qp = Q + (size_t)nh * L * DH + (size_t)qb * 64 * DH;
    const float* Kp = K + (size_t)nh * L * DH;
    const float* Vp = V + (size_t)nh * L * DH;

    // load Q tile transposed to [d][r]
    for (int i = tid; i < 64 * 16; i += 256) {
        int r = i >> 4, d4 = (i & 15) << 2;
        float4 v = *(const float4*)(Qp + r * DH + d4);
        Qs[(d4 + 0) * 64 + r] = v.x;
        Qs[(d4 + 1) * 64 + r] = v.y;
        Qs[(d4 + 2) * 64 + r] = v.z;
        Qs[(d4 + 3) * 64 + r] = v.w;
    }
    if (tid < 64) { mrow[tid] = -1e30f; lrow[tid] = 0.f; }
    float acc[4][4] = {};
    __syncthreads();

    for (int jb = 0; jb < 64; ++jb) {
        const float* Kb = Kp + (size_t)jb * 64 * DH;
        const float* Vb = Vp + (size_t)jb * 64 * DH;
        for (int i = tid; i < 64 * 16; i += 256) {
            int r = i >> 4, d4 = (i & 15) << 2;
            float4 kv = *(const float4*)(Kb + r * DH + d4);
            Ks[(d4 + 0) * 64 + r] = kv.x;
            Ks[(d4 + 1) * 64 + r] = kv.y;
            Ks[(d4 + 2) * 64 + r] = kv.z;
            Ks[(d4 + 3) * 64 + r] = kv.w;
            *(float4*)(Vs + r * 64 + d4) = *(const float4*)(Vb + r * DH + d4);
        }
        __syncthreads();

        // S = (Q K^T) * 1/8
        float s[4][4] = {};
#pragma unroll 16
        for (int d = 0; d < 64; ++d) {
            float4 a = *(const float4*)(Qs + d * 64 + ty * 4);
            float4 b = *(const float4*)(Ks + d * 64 + tx * 4);
            s[0][0] += a.x*b.x; s[0][1] += a.x*b.y; s[0][2] += a.x*b.z; s[0][3] += a.x*b.w;
            s[1][0] += a.y*b.x; s[1][1] += a.y*b.y; s[1][2] += a.y*b.z; s[1][3] += a.y*b.w;
            s[2][0] += a.z*b.x; s[2][1] += a.z*b.y; s[2][2] += a.z*b.z; s[2][3] += a.z*b.w;
            s[3][0] += a.w*b.x; s[3][1] += a.w*b.y; s[3][2] += a.w*b.z; s[3][3] += a.w*b.w;
        }
#pragma unroll
        for (int i = 0; i < 4; ++i)
#pragma unroll
            for (int j = 0; j < 4; ++j)
                Ss[(ty * 4 + i) * 65 + tx * 4 + j] = s[i][j] * 0.125f;
        __syncthreads();

        // online softmax: warp w owns rows [w*8, w*8+8)
        {
            int lane = tid & 31, w = tid >> 5;
#pragma unroll
            for (int rr = 0; rr < 8; ++rr) {
                int r = w * 8 + rr;
                float v0 = Ss[r * 65 + lane], v1 = Ss[r * 65 + lane + 32];
                float mx = fmaxf(v0, v1);
#pragma unroll
                for (int off = 16; off; off >>= 1)
                    mx = fmaxf(mx, __shfl_xor_sync(0xffffffffu, mx, off));
                float mo = mrow[r];
                float mn = fmaxf(mo, mx);
                float p0 = __expf(v0 - mn), p1 = __expf(v1 - mn);
                float ps = p0 + p1;
#pragma unroll
                for (int off = 16; off; off >>= 1)
                    ps += __shfl_xor_sync(0xffffffffu, ps, off);
                Ss[r * 65 + lane] = p0;
                Ss[r * 65 + lane + 32] = p1;
                if (lane == 0) {
                    float corr = __expf(mo - mn);
                    lrow[r] = lrow[r] * corr + ps;
                    mrow[r] = mn;
                    srow[r] = corr;
                }
            }
        }
        __syncthreads();

        // O = O*corr + P @ V
#pragma unroll
        for (int i = 0; i < 4; ++i) {
            float c_ = srow[ty * 4 + i];
#pragma unroll
            for (int j = 0; j < 4; ++j) acc[i][j] *= c_;
        }
#pragma unroll 16
        for (int m = 0; m < 64; ++m) {
            float a0 = Ss[(ty * 4 + 0) * 65 + m];
            float a1 = Ss[(ty * 4 + 1) * 65 + m];
            float a2 = Ss[(ty * 4 + 2) * 65 + m];
            float a3 = Ss[(ty * 4 + 3) * 65 + m];
            float4 b = *(const float4*)(Vs + m * 64 + tx * 4);
            acc[0][0] += a0*b.x; acc[0][1] += a0*b.y; acc[0][2] += a0*b.z; acc[0][3] += a0*b.w;
            acc[1][0] += a1*b.x; acc[1][1] += a1*b.y; acc[1][2] += a1*b.z; acc[1][3] += a1*b.w;
            acc[2][0] += a2*b.x; acc[2][1] += a2*b.y; acc[2][2] += a2*b.z; acc[2][3] += a2*b.w;
            acc[3][0] += a3*b.x; acc[3][1] += a3*b.y; acc[3][2] += a3*b.z; acc[3][3] += a3*b.w;
        }
        __syncthreads();
    }

    // write [n][c=h*64+d][l]
#pragma unroll
    for (int i = 0; i < 4; ++i) {
        int r = ty * 4 + i;
        float invl = 1.f / lrow[r];
#pragma unroll
        for (int j = 0; j < 4; ++j) {
            int d = tx * 4 + j;
            AO[((size_t)n * C + h * 64 + d) * L + (size_t)qb * 64 + r] = acc[i][j] * invl;
        }
    }
}

// ---------------- launch ----------------
extern "C" void kernel_launch(void* const* d_in, const int* in_sizes, int n_in,
                              void* d_out, int out_size) {
    const float* x     = (const float*)d_in[0];
    const float* gamma = (const float*)d_in[1];
    const float* beta  = (const float*)d_in[2];
    const float* Wq    = (const float*)d_in[3];
    const float* Wk    = (const float*)d_in[4];
    const float* Wv    = (const float*)d_in[5];
    const float* Wp    = (const float*)d_in[6];
    const float* bp    = (const float*)d_in[7];
    float* out = (float*)d_out;

    void *p_xn, *p_q, *p_k, *p_v, *p_ao;
    cudaGetSymbolAddress(&p_xn, g_xn);
    cudaGetSymbolAddress(&p_q,  g_q);
    cudaGetSymbolAddress(&p_k,  g_k);
    cudaGetSymbolAddress(&p_v,  g_v);
    cudaGetSymbolAddress(&p_ao, g_ao);

    gn_kernel<<<NB * GROUPS, 256>>>(x, gamma, beta, (float*)p_xn);

    dim3 pb(16, 16), pg(L / 64, C / 64, NB);
    proj_kernel<<<pg, pb>>>(Wq, (const float*)p_xn, (float*)p_q, nullptr, 0);
    proj_kernel<<<pg, pb>>>(Wk, (const float*)p_xn, (float*)p_k, nullptr, 0);
    proj_kernel<<<pg, pb>>>(Wv, (const float*)p_xn, (float*)p_v, nullptr, 0);

    int smem = ATTN_SMEM_FLOATS * (int)sizeof(float);
    cudaFuncSetAttribute(attn_kernel, cudaFuncAttributeMaxDynamicSharedMemorySize, smem);
    attn_kernel<<<dim3(L / 64, NB * HEADS), 256, smem>>>(
        (const float*)p_q, (const float*)p_k, (const float*)p_v, (float*)p_ao);

    proj_kernel<<<pg, pb>>>(Wp, (const float*)p_ao, out, bp, 1);
}

// round 2
// speedup vs baseline: 3.1747x; 3.1747x over previous
#include <cuda_runtime.h>
#include <cstdint>

#define NB     4
#define C      256
#define L      4096
#define GROUPS 32
#define CPG    8
#define HEADS  4
#define DH     64
#define EPS    1e-5f

#define BR 128        // q rows per block
#define BC 64         // kv cols per iteration
#define NJB (L / BC)
#define KP 68         // K smem pitch (floats)
#define VP 72         // V smem pitch (floats)
#define BUF (BC * KP + BC * VP)   // floats per double-buffer slot

// ---------------- scratch ----------------
__device__ float g_xn[(size_t)NB * C * L];
__device__ float g_q [(size_t)NB * HEADS * L * DH];
__device__ float g_k [(size_t)NB * HEADS * L * DH];
__device__ float g_v [(size_t)NB * HEADS * L * DH];
__device__ float g_ao[(size_t)NB * C * L];

// ---------------- helpers ----------------
__device__ __forceinline__ uint32_t f2tf32(float x) {
    uint32_t u;
    asm("cvt.rna.tf32.f32 %0, %1;" : "=r"(u) : "f"(x));
    return u;
}
__device__ __forceinline__ uint32_t smem_u32(const void* p) {
    return (uint32_t)__cvta_generic_to_shared(p);
}
__device__ __forceinline__ void cp16(uint32_t saddr, const void* g) {
    asm volatile("cp.async.cg.shared.global [%0], [%1], 16;" :: "r"(saddr), "l"(g));
}
__device__ __forceinline__ void cp_commit() {
    asm volatile("cp.async.commit_group;");
}
__device__ __forceinline__ void cp_wait1() {
    asm volatile("cp.async.wait_group 1;");
}
__device__ __forceinline__ void mma_tf32(float c[4],
                                         uint32_t a0, uint32_t a1, uint32_t a2, uint32_t a3,
                                         uint32_t b0, uint32_t b1) {
    asm volatile(
        "mma.sync.aligned.m16n8k8.row.col.f32.tf32.tf32.f32 "
        "{%0,%1,%2,%3},{%4,%5,%6,%7},{%8,%9},{%0,%1,%2,%3};"
        : "+f"(c[0]), "+f"(c[1]), "+f"(c[2]), "+f"(c[3])
        : "r"(a0), "r"(a1), "r"(a2), "r"(a3), "r"(b0), "r"(b1));
}

// ---------------- GroupNorm ----------------
__global__ __launch_bounds__(256) void gn_kernel(const float* __restrict__ x,
                                                 const float* __restrict__ gamma,
                                                 const float* __restrict__ beta,
                                                 float* __restrict__ xn) {
    int n = blockIdx.x >> 5, g = blockIdx.x & 31;
    size_t base = ((size_t)n * C + g * CPG) * L;
    const float4* xp = (const float4*)(x + base);
    float s = 0.f, ss = 0.f;
    const int NV = CPG * L / 4;
    for (int i = threadIdx.x; i < NV; i += 256) {
        float4 v = xp[i];
        s  += v.x + v.y + v.z + v.w;
        ss += v.x*v.x + v.y*v.y + v.z*v.z + v.w*v.w;
    }
    __shared__ float rs[256], rq[256];
    rs[threadIdx.x] = s; rq[threadIdx.x] = ss;
    __syncthreads();
    for (int off = 128; off; off >>= 1) {
        if (threadIdx.x < off) {
            rs[threadIdx.x] += rs[threadIdx.x + off];
            rq[threadIdx.x] += rq[threadIdx.x + off];
        }
        __syncthreads();
    }
    float mean = rs[0] * (1.f / (CPG * L));
    float var  = rq[0] * (1.f / (CPG * L)) - mean * mean;
    float inv  = rsqrtf(var + EPS);
    float4* op = (float4*)(xn + base);
    for (int i = threadIdx.x; i < NV; i += 256) {
        int c = g * CPG + (i >> 10);
        float gm = gamma[c] * inv;
        float bt = beta[c] - mean * gm;
        float4 v = xp[i];
        float4 o;
        o.x = v.x * gm + bt; o.y = v.y * gm + bt;
        o.z = v.z * gm + bt; o.w = v.w * gm + bt;
        op[i] = o;
    }
}

// ---------------- 1x1-conv GEMM ----------------
// mode 0: write [n][h][l][d], rounded to tf32, scaled by oscale
// mode 1: write [n][c][l] + bias (fp32)
__global__ __launch_bounds__(256) void proj_kernel(const float* __restrict__ Wm,
                                                   const float* __restrict__ X,
                                                   float* __restrict__ out,
                                                   const float* __restrict__ bias,
                                                   int mode, float oscale) {
    __shared__ float Ws[16][64];
    __shared__ float Xs[16][64];
    int n = blockIdx.z;
    int obase = blockIdx.y * 64;
    int lbase = blockIdx.x * 64;
    const float* Xn = X + (size_t)n * C * L;
    int tid = threadIdx.y * 16 + threadIdx.x;
    float acc[4][4] = {};
    for (int kb = 0; kb < C; kb += 16) {
        {
            int ol = tid >> 2, k4 = (tid & 3) * 4;
            float4 w = *(const float4*)&Wm[(size_t)(obase + ol) * C + kb + k4];
            Ws[k4 + 0][ol] = w.x; Ws[k4 + 1][ol] = w.y;
            Ws[k4 + 2][ol] = w.z; Ws[k4 + 3][ol] = w.w;
        }
        {
            int cl = tid >> 4, l4 = (tid & 15) * 4;
            *(float4*)&Xs[cl][l4] =
                *(const float4*)&Xn[(size_t)(kb + cl) * L + lbase + l4];
        }
        __syncthreads();
#pragma unroll
        for (int k = 0; k < 16; ++k) {
            float4 a = *(const float4*)&Ws[k][threadIdx.y * 4];
            float4 b = *(const float4*)&Xs[k][threadIdx.x * 4];
            acc[0][0] += a.x*b.x; acc[0][1] += a.x*b.y; acc[0][2] += a.x*b.z; acc[0][3] += a.x*b.w;
            acc[1][0] += a.y*b.x; acc[1][1] += a.y*b.y; acc[1][2] += a.y*b.z; acc[1][3] += a.y*b.w;
            acc[2][0] += a.z*b.x; acc[2][1] += a.z*b.y; acc[2][2] += a.z*b.z; acc[2][3] += a.z*b.w;
            acc[3][0] += a.w*b.x; acc[3][1] += a.w*b.y; acc[3][2] += a.w*b.z; acc[3][3] += a.w*b.w;
        }
        __syncthreads();
    }
    if (mode == 0) {
        int h = obase >> 6;
        float* outp = out + ((size_t)(n * HEADS + h)) * L * DH;
#pragma unroll
        for (int i = 0; i < 4; ++i) {
            int d = threadIdx.y * 4 + i;
#pragma unroll
            for (int j = 0; j < 4; ++j) {
                int l = lbase + threadIdx.x * 4 + j;
                outp[(size_t)l * DH + d] = __uint_as_float(f2tf32(acc[i][j] * oscale));
            }
        }
    } else {
#pragma unroll
        for (int i = 0; i < 4; ++i) {
            int o = obase + threadIdx.y * 4 + i;
            float bv = bias[o];
#pragma unroll
            for (int j = 0; j < 4; ++j) {
                out[((size_t)n * C + o) * L + lbase + threadIdx.x * 4 + j] = acc[i][j] + bv;
            }
        }
    }
}

// ---------------- tf32 tensor-core flash attention ----------------
// grid (L/BR, NB*HEADS), block 256 = 8 warps; warp w owns q-rows [16w,16w+16)
__global__ __launch_bounds__(256, 2) void attn_kernel(const float* __restrict__ Q,
                                                      const float* __restrict__ K,
                                                      const float* __restrict__ V,
                                                      float* __restrict__ AO) {
    extern __shared__ float sm[];
    const uint32_t sbase = smem_u32(sm);

    const int tid  = threadIdx.x;
    const int lane = tid & 31;
    const int w    = tid >> 5;
    const int g    = lane >> 2;
    const int tig  = lane & 3;
    const int qb   = blockIdx.x;
    const int nh   = blockIdx.y;
    const int n    = nh >> 2, h = nh & 3;

    const float* Qp = Q + (size_t)nh * L * DH + ((size_t)qb * BR + w * 16) * DH;
    const float* Kg = K + (size_t)nh * L * DH;
    const float* Vg = V + (size_t)nh * L * DH;

    // Q A-fragments (already tf32-rounded & prescaled by 1/8 at projection)
    uint32_t aq[8][4];
#pragma unroll
    for (int kc = 0; kc < 8; ++kc) {
        aq[kc][0] = __float_as_uint(Qp[(size_t)g        * DH + 8 * kc + tig]);
        aq[kc][1] = __float_as_uint(Qp[(size_t)(g + 8)  * DH + 8 * kc + tig]);
        aq[kc][2] = __float_as_uint(Qp[(size_t)g        * DH + 8 * kc + tig + 4]);
        aq[kc][3] = __float_as_uint(Qp[(size_t)(g + 8)  * DH + 8 * kc + tig + 4]);
    }

    float m0 = -1e30f, m1 = -1e30f, l0 = 0.f, l1 = 0.f;
    float acc[8][4] = {};

    // stage K/V tile jb into buffer buf
    auto stage = [&](int jb, int buf) {
        uint32_t kb = sbase + (uint32_t)(buf * BUF) * 4u;
        uint32_t vb = kb + (uint32_t)(BC * KP) * 4u;
        const float* Ks = Kg + (size_t)jb * BC * DH;
        const float* Vs = Vg + (size_t)jb * BC * DH;
#pragma unroll
        for (int it = 0; it < 4; ++it) {
            int i = tid + it * 256;         // 1024 16B-chunks
            int j = i >> 4, dq = i & 15;
            cp16(kb + (uint32_t)(j * KP + dq * 4) * 4u, Ks + (size_t)j * DH + dq * 4);
        }
#pragma unroll
        for (int it = 0; it < 4; ++it) {
            int i = tid + it * 256;
            int j = i >> 4, dq = i & 15;
            cp16(vb + (uint32_t)(j * VP + dq * 4) * 4u, Vs + (size_t)j * DH + dq * 4);
        }
    };

    stage(0, 0);
    cp_commit();

    for (int jb = 0; jb < NJB; ++jb) {
        if (jb + 1 < NJB) stage(jb + 1, (jb + 1) & 1);
        cp_commit();
        cp_wait1();
        __syncthreads();

        const float* bK = sm + (jb & 1) * BUF;
        const float* bV = bK + BC * KP;

        // ---- S = Q K^T (scale folded into Q) ----
        float c[8][4] = {};
#pragma unroll
        for (int kc = 0; kc < 8; ++kc) {
#pragma unroll
            for (int nc = 0; nc < 8; ++nc) {
                const float* kp = bK + (8 * nc + g) * KP + 8 * kc + tig;
                uint32_t b0 = __float_as_uint(kp[0]);
                uint32_t b1 = __float_as_uint(kp[4]);
                mma_tf32(c[nc], aq[kc][0], aq[kc][1], aq[kc][2], aq[kc][3], b0, b1);
            }
        }

        // ---- online softmax (registers + quad shuffles) ----
        float mx0 = -1e30f, mx1 = -1e30f;
#pragma unroll
        for (int nc = 0; nc < 8; ++nc) {
            mx0 = fmaxf(mx0, fmaxf(c[nc][0], c[nc][1]));
            mx1 = fmaxf(mx1, fmaxf(c[nc][2], c[nc][3]));
        }
        mx0 = fmaxf(mx0, __shfl_xor_sync(0xffffffffu, mx0, 1));
        mx0 = fmaxf(mx0, __shfl_xor_sync(0xffffffffu, mx0, 2));
        mx1 = fmaxf(mx1, __shfl_xor_sync(0xffffffffu, mx1, 1));
        mx1 = fmaxf(mx1, __shfl_xor_sync(0xffffffffu, mx1, 2));

        float mn0 = fmaxf(m0, mx0), mn1 = fmaxf(m1, mx1);
        float cr0 = __expf(m0 - mn0), cr1 = __expf(m1 - mn1);
        m0 = mn0; m1 = mn1;

        float ps0 = 0.f, ps1 = 0.f;
#pragma unroll
        for (int nc = 0; nc < 8; ++nc) {
            c[nc][0] = __expf(c[nc][0] - mn0);
            c[nc][1] = __expf(c[nc][1] - mn0);
            c[nc][2] = __expf(c[nc][2] - mn1);
            c[nc][3] = __expf(c[nc][3] - mn1);
            ps0 += c[nc][0] + c[nc][1];
            ps1 += c[nc][2] + c[nc][3];
        }
        ps0 += __shfl_xor_sync(0xffffffffu, ps0, 1);
        ps0 += __shfl_xor_sync(0xffffffffu, ps0, 2);
        ps1 += __shfl_xor_sync(0xffffffffu, ps1, 1);
        ps1 += __shfl_xor_sync(0xffffffffu, ps1, 2);
        l0 = l0 * cr0 + ps0;
        l1 = l1 * cr1 + ps1;

        // rescale O accumulator
#pragma unroll
        for (int nc = 0; nc < 8; ++nc) {
            acc[nc][0] *= cr0; acc[nc][1] *= cr0;
            acc[nc][2] *= cr1; acc[nc][3] *= cr1;
        }

        // round P to tf32 in place
#pragma unroll
        for (int nc = 0; nc < 8; ++nc)
#pragma unroll
            for (int i = 0; i < 4; ++i)
                c[nc][i] = __uint_as_float(f2tf32(c[nc][i]));

        // ---- O += P V ----  (C-frag -> A-frag via intra-quad shuffles)
        const int srcA = (lane & 28) | (tig >> 1);
        const int srcB = srcA | 2;
        const bool odd = tig & 1;
#pragma unroll
        for (int kc = 0; kc < 8; ++kc) {
            float x0 = __shfl_sync(0xffffffffu, c[kc][0], srcA);
            float x1 = __shfl_sync(0xffffffffu, c[kc][1], srcA);
            float x2 = __shfl_sync(0xffffffffu, c[kc][2], srcA);
            float x3 = __shfl_sync(0xffffffffu, c[kc][3], srcA);
            float y0 = __shfl_sync(0xffffffffu, c[kc][0], srcB);
            float y1 = __shfl_sync(0xffffffffu, c[kc][1], srcB);
            float y2 = __shfl_sync(0xffffffffu, c[kc][2], srcB);
            float y3 = __shfl_sync(0xffffffffu, c[kc][3], srcB);
            uint32_t p0 = __float_as_uint(odd ? x1 : x0);
            uint32_t p1 = __float_as_uint(odd ? x3 : x2);
            uint32_t p2 = __float_as_uint(odd ? y1 : y0);
            uint32_t p3 = __float_as_uint(odd ? y3 : y2);
#pragma unroll
            for (int nc = 0; nc < 8; ++nc) {
                const float* vp = bV + (8 * kc + tig) * VP + 8 * nc + g;
                uint32_t b0 = __float_as_uint(vp[0]);
                uint32_t b1 = __float_as_uint(vp[4 * VP]);
                mma_tf32(acc[nc], p0, p1, p2, p3, b0, b1);
            }
        }
        __syncthreads();
    }

    // ---- write O / l to [n][c][l] ----
    float il0 = 1.f / l0, il1 = 1.f / l1;
    int q0 = qb * BR + w * 16 + g;
    int q1 = q0 + 8;
    float* aoB = AO + (size_t)n * C * L + (size_t)h * 64 * L;
#pragma unroll
    for (int nc = 0; nc < 8; ++nc) {
        int d0 = 8 * nc + 2 * tig;
        aoB[(size_t)d0 * L + q0]       = acc[nc][0] * il0;
        aoB[(size_t)(d0 + 1) * L + q0] = acc[nc][1] * il0;
        aoB[(size_t)d0 * L + q1]       = acc[nc][2] * il1;
        aoB[(size_t)(d0 + 1) * L + q1] = acc[nc][3] * il1;
    }
}

// ---------------- launch ----------------
extern "C" void kernel_launch(void* const* d_in, const int* in_sizes, int n_in,
                              void* d_out, int out_size) {
    const float* x     = (const float*)d_in[0];
    const float* gamma = (const float*)d_in[1];
    const float* beta  = (const float*)d_in[2];
    const float* Wq    = (const float*)d_in[3];
    const float* Wk    = (const float*)d_in[4];
    const float* Wv    = (const float*)d_in[5];
    const float* Wp    = (const float*)d_in[6];
    const float* bp    = (const float*)d_in[7];
    float* out = (float*)d_out;

    void *p_xn, *p_q, *p_k, *p_v, *p_ao;
    cudaGetSymbolAddress(&p_xn, g_xn);
    cudaGetSymbolAddress(&p_q,  g_q);
    cudaGetSymbolAddress(&p_k,  g_k);
    cudaGetSymbolAddress(&p_v,  g_v);
    cudaGetSymbolAddress(&p_ao, g_ao);

    gn_kernel<<<NB * GROUPS, 256>>>(x, gamma, beta, (float*)p_xn);

    dim3 pb(16, 16), pg(L / 64, C / 64, NB);
    proj_kernel<<<pg, pb>>>(Wq, (const float*)p_xn, (float*)p_q, nullptr, 0, 0.125f);
    proj_kernel<<<pg, pb>>>(Wk, (const float*)p_xn, (float*)p_k, nullptr, 0, 1.0f);
    proj_kernel<<<pg, pb>>>(Wv, (const float*)p_xn, (float*)p_v, nullptr, 0, 1.0f);

    int smem = BUF * 2 * (int)sizeof(float);
    cudaFuncSetAttribute(attn_kernel, cudaFuncAttributeMaxDynamicSharedMemorySize, smem);
    attn_kernel<<<dim3(L / BR, NB * HEADS), 256, smem>>>(
        (const float*)p_q, (const float*)p_k, (const float*)p_v, (float*)p_ao);

    proj_kernel<<<pg, pb>>>(Wp, (const float*)p_ao, out, bp, 1, 0.f);
}

// round 5
// speedup vs baseline: 4.1391x; 1.3038x over previous
#include <cuda_runtime.h>
#include <cstdint>

#define NB     4
#define C      256
#define L      4096
#define GROUPS 32
#define CPG    8
#define HEADS  4
#define DH     64
#define EPS    1e-5f

// attention tiling
#define BR 128
#define BC 64
#define NJB (L / BC)
#define KP 68
#define VP 72
#define BUF (BC * KP + BC * VP)

// projection tiling
#define PBK 32
#define XP  132
#define WP  36
#define XS_FLOATS (PBK * XP)
#define WS_FLOATS (128 * WP)
#define PROJ_SMEM ((2 * XS_FLOATS + 2 * WS_FLOATS) * 4)

// ---------------- scratch ----------------
__device__ float g_xn[(size_t)NB * C * L];
__device__ float g_q [(size_t)NB * HEADS * L * DH];
__device__ float g_k [(size_t)NB * HEADS * L * DH];
__device__ float g_v [(size_t)NB * HEADS * L * DH];
__device__ float g_ao[(size_t)NB * C * L];
__device__ float g_wr[4 * C * C];          // tf32-rounded Wq,Wk,Wv,Wp

// ---------------- helpers ----------------
__device__ __forceinline__ uint32_t f2tf32(float x) {
    uint32_t u;
    asm("cvt.rna.tf32.f32 %0, %1;" : "=r"(u) : "f"(x));
    return u;
}
__device__ __forceinline__ float f2tf32f(float x) {
    return __uint_as_float(f2tf32(x));
}
__device__ __forceinline__ uint32_t smem_u32(const void* p) {
    return (uint32_t)__cvta_generic_to_shared(p);
}
__device__ __forceinline__ void cp16(uint32_t saddr, const void* g) {
    asm volatile("cp.async.cg.shared.global [%0], [%1], 16;" :: "r"(saddr), "l"(g));
}
__device__ __forceinline__ void cp_commit() {
    asm volatile("cp.async.commit_group;");
}
__device__ __forceinline__ void cp_wait1() {
    asm volatile("cp.async.wait_group 1;");
}
__device__ __forceinline__ void mma_tf32(float c[4],
                                         uint32_t a0, uint32_t a1, uint32_t a2, uint32_t a3,
                                         uint32_t b0, uint32_t b1) {
    asm volatile(
        "mma.sync.aligned.m16n8k8.row.col.f32.tf32.tf32.f32 "
        "{%0,%1,%2,%3},{%4,%5,%6,%7},{%8,%9},{%0,%1,%2,%3};"
        : "+f"(c[0]), "+f"(c[1]), "+f"(c[2]), "+f"(c[3])
        : "r"(a0), "r"(a1), "r"(a2), "r"(a3), "r"(b0), "r"(b1));
}

// ---------------- weight pre-round (rna -> tf32) ----------------
__global__ __launch_bounds__(256) void wround_kernel(const float* __restrict__ w0,
                                                     const float* __restrict__ w1,
                                                     const float* __restrict__ w2,
                                                     const float* __restrict__ w3,
                                                     float* __restrict__ outw) {
    const float* srcs[4] = {w0, w1, w2, w3};
    int m = blockIdx.y;
    const float4* s = (const float4*)srcs[m];
    float4* d = (float4*)(outw + (size_t)m * C * C);
    int i = blockIdx.x * 256 + threadIdx.x;   // C*C/4 = 16384 float4s
    float4 v = s[i];
    v.x = f2tf32f(v.x); v.y = f2tf32f(v.y);
    v.z = f2tf32f(v.z); v.w = f2tf32f(v.w);
    d[i] = v;
}

// ---------------- GroupNorm (output rounded to tf32) ----------------
__global__ __launch_bounds__(256) void gn_kernel(const float* __restrict__ x,
                                                 const float* __restrict__ gamma,
                                                 const float* __restrict__ beta,
                                                 float* __restrict__ xn) {
    int n = blockIdx.x >> 5, g = blockIdx.x & 31;
    size_t base = ((size_t)n * C + g * CPG) * L;
    const float4* xp = (const float4*)(x + base);
    float s = 0.f, ss = 0.f;
    const int NV = CPG * L / 4;
    for (int i = threadIdx.x; i < NV; i += 256) {
        float4 v = xp[i];
        s  += v.x + v.y + v.z + v.w;
        ss += v.x*v.x + v.y*v.y + v.z*v.z + v.w*v.w;
    }
    __shared__ float rs[256], rq[256];
    rs[threadIdx.x] = s; rq[threadIdx.x] = ss;
    __syncthreads();
    for (int off = 128; off; off >>= 1) {
        if (threadIdx.x < off) {
            rs[threadIdx.x] += rs[threadIdx.x + off];
            rq[threadIdx.x] += rq[threadIdx.x + off];
        }
        __syncthreads();
    }
    float mean = rs[0] * (1.f / (CPG * L));
    float var  = rq[0] * (1.f / (CPG * L)) - mean * mean;
    float inv  = rsqrtf(var + EPS);
    float4* op = (float4*)(xn + base);
    for (int i = threadIdx.x; i < NV; i += 256) {
        int c = g * CPG + (i >> 10);
        float gm = gamma[c] * inv;
        float bt = beta[c] - mean * gm;
        float4 v = xp[i];
        float4 o;
        o.x = f2tf32f(v.x * gm + bt); o.y = f2tf32f(v.y * gm + bt);
        o.z = f2tf32f(v.z * gm + bt); o.w = f2tf32f(v.w * gm + bt);
        op[i] = o;
    }
}

// ---------------- tf32 tensor-core 1x1-conv GEMM ----------------
// (inputs X and W are pre-rounded to tf32, so HW truncation is exact)
__global__ __launch_bounds__(256, 2) void proj_kernel(const float* __restrict__ Wm,
                                                      const float* __restrict__ X,
                                                      float* __restrict__ out,
                                                      const float* __restrict__ bias,
                                                      int mode, float oscale) {
    extern __shared__ float psm[];
    float* Xs = psm;
    float* Ws = psm + 2 * XS_FLOATS;
    const uint32_t xbase = smem_u32(Xs);
    const uint32_t wbase = smem_u32(Ws);

    const int tid  = threadIdx.x;
    const int lane = tid & 31;
    const int w    = tid >> 5;
    const int g    = lane >> 2;
    const int tig  = lane & 3;
    const int mwarp = (w >> 2) * 64;
    const int nwarp = (w & 3) * 32;

    const int n     = blockIdx.z;
    const int lbase = blockIdx.x * 128;
    const int obase = blockIdx.y * 128;
    const float* Xn = X + (size_t)n * C * L;

    float acc[4][4][4] = {};

    auto stage = [&](int s, int buf) {
        int cb = s * PBK;
        uint32_t xb = xbase + (uint32_t)(buf * XS_FLOATS) * 4u;
        uint32_t wb = wbase + (uint32_t)(buf * WS_FLOATS) * 4u;
#pragma unroll
        for (int it = 0; it < 4; ++it) {
            int i = tid + it * 256;
            int c = i >> 5, l4 = (i & 31) * 4;
            cp16(xb + (uint32_t)(c * XP + l4) * 4u,
                 Xn + (size_t)(cb + c) * L + lbase + l4);
        }
#pragma unroll
        for (int it = 0; it < 4; ++it) {
            int i = tid + it * 256;
            int o = i >> 3, c4 = (i & 7) * 4;
            cp16(wb + (uint32_t)(o * WP + c4) * 4u,
                 Wm + (size_t)(obase + o) * C + cb + c4);
        }
    };

    stage(0, 0);
    cp_commit();

    const int NSTG = C / PBK;
    for (int s = 0; s < NSTG; ++s) {
        if (s + 1 < NSTG) stage(s + 1, (s + 1) & 1);
        cp_commit();
        cp_wait1();
        __syncthreads();

        const float* bX = Xs + (s & 1) * XS_FLOATS;
        const float* bW = Ws + (s & 1) * WS_FLOATS;

#pragma unroll
        for (int kc = 0; kc < PBK; kc += 8) {
            uint32_t bf[4][2];
#pragma unroll
            for (int ni = 0; ni < 4; ++ni) {
                const float* wp = bW + (nwarp + ni * 8 + g) * WP + kc + tig;
                bf[ni][0] = __float_as_uint(wp[0]);
                bf[ni][1] = __float_as_uint(wp[4]);
            }
#pragma unroll
            for (int mi = 0; mi < 4; ++mi) {
                const float* xr0 = bX + (kc + tig) * XP + mwarp + mi * 16;
                const float* xr1 = bX + (kc + tig + 4) * XP + mwarp + mi * 16;
                uint32_t a0 = __float_as_uint(xr0[g]);
                uint32_t a1 = __float_as_uint(xr0[g + 8]);
                uint32_t a2 = __float_as_uint(xr1[g]);
                uint32_t a3 = __float_as_uint(xr1[g + 8]);
#pragma unroll
                for (int ni = 0; ni < 4; ++ni)
                    mma_tf32(acc[mi][ni], a0, a1, a2, a3, bf[ni][0], bf[ni][1]);
            }
        }
        __syncthreads();
    }

    if (mode == 0) {
#pragma unroll
        for (int mi = 0; mi < 4; ++mi) {
            int l0 = lbase + mwarp + mi * 16 + g;
#pragma unroll
            for (int ni = 0; ni < 4; ++ni) {
                int o = obase + nwarp + ni * 8 + 2 * tig;
                int h = o >> 6, d = o & 63;
                float* op = out + ((size_t)(n * HEADS + h) * L) * DH + d;
                float2 v0, v1;
                v0.x = f2tf32f(acc[mi][ni][0] * oscale);
                v0.y = f2tf32f(acc[mi][ni][1] * oscale);
                v1.x = f2tf32f(acc[mi][ni][2] * oscale);
                v1.y = f2tf32f(acc[mi][ni][3] * oscale);
                *(float2*)(op + (size_t)l0 * DH)       = v0;
                *(float2*)(op + (size_t)(l0 + 8) * DH) = v1;
            }
        }
    } else {
#pragma unroll
        for (int mi = 0; mi < 4; ++mi) {
            int l0 = lbase + mwarp + mi * 16 + g;
#pragma unroll
            for (int ni = 0; ni < 4; ++ni) {
                int o = obase + nwarp + ni * 8 + 2 * tig;
                float b0 = bias[o], b1 = bias[o + 1];
                float* op = out + (size_t)n * C * L;
                op[(size_t)o * L + l0]             = acc[mi][ni][0] + b0;
                op[(size_t)(o + 1) * L + l0]       = acc[mi][ni][1] + b1;
                op[(size_t)o * L + l0 + 8]         = acc[mi][ni][2] + b0;
                op[(size_t)(o + 1) * L + l0 + 8]   = acc[mi][ni][3] + b1;
            }
        }
    }
}

// ---------------- tf32 tensor-core flash attention ----------------
__global__ __launch_bounds__(256, 2) void attn_kernel(const float* __restrict__ Q,
                                                      const float* __restrict__ K,
                                                      const float* __restrict__ V,
                                                      float* __restrict__ AO) {
    extern __shared__ float sm[];
    const uint32_t sbase = smem_u32(sm);

    const int tid  = threadIdx.x;
    const int lane = tid & 31;
    const int w    = tid >> 5;
    const int g    = lane >> 2;
    const int tig  = lane & 3;
    const int qb   = blockIdx.x;
    const int nh   = blockIdx.y;
    const int n    = nh >> 2, h = nh & 3;

    const float* Qp = Q + (size_t)nh * L * DH + ((size_t)qb * BR + w * 16) * DH;
    const float* Kg = K + (size_t)nh * L * DH;
    const float* Vg = V + (size_t)nh * L * DH;

    uint32_t aq[8][4];
#pragma unroll
    for (int kc = 0; kc < 8; ++kc) {
        aq[kc][0] = __float_as_uint(Qp[(size_t)g        * DH + 8 * kc + tig]);
        aq[kc][1] = __float_as_uint(Qp[(size_t)(g + 8)  * DH + 8 * kc + tig]);
        aq[kc][2] = __float_as_uint(Qp[(size_t)g        * DH + 8 * kc + tig + 4]);
        aq[kc][3] = __float_as_uint(Qp[(size_t)(g + 8)  * DH + 8 * kc + tig + 4]);
    }

    float m0 = -1e30f, m1 = -1e30f, l0 = 0.f, l1 = 0.f;
    float acc[8][4] = {};

    auto stage = [&](int jb, int buf) {
        uint32_t kb = sbase + (uint32_t)(buf * BUF) * 4u;
        uint32_t vb = kb + (uint32_t)(BC * KP) * 4u;
        const float* Ks = Kg + (size_t)jb * BC * DH;
        const float* Vs = Vg + (size_t)jb * BC * DH;
#pragma unroll
        for (int it = 0; it < 4; ++it) {
            int i = tid + it * 256;
            int j = i >> 4, dq = i & 15;
            cp16(kb + (uint32_t)(j * KP + dq * 4) * 4u, Ks + (size_t)j * DH + dq * 4);
        }
#pragma unroll
        for (int it = 0; it < 4; ++it) {
            int i = tid + it * 256;
            int j = i >> 4, dq = i & 15;
            cp16(vb + (uint32_t)(j * VP + dq * 4) * 4u, Vs + (size_t)j * DH + dq * 4);
        }
    };

    stage(0, 0);
    cp_commit();

    for (int jb = 0; jb < NJB; ++jb) {
        if (jb + 1 < NJB) stage(jb + 1, (jb + 1) & 1);
        cp_commit();
        cp_wait1();
        __syncthreads();

        const float* bK = sm + (jb & 1) * BUF;
        const float* bV = bK + BC * KP;

        float c[8][4] = {};
#pragma unroll
        for (int kc = 0; kc < 8; ++kc) {
#pragma unroll
            for (int nc = 0; nc < 8; ++nc) {
                const float* kp = bK + (8 * nc + g) * KP + 8 * kc + tig;
                uint32_t b0 = __float_as_uint(kp[0]);
                uint32_t b1 = __float_as_uint(kp[4]);
                mma_tf32(c[nc], aq[kc][0], aq[kc][1], aq[kc][2], aq[kc][3], b0, b1);
            }
        }

        float mx0 = -1e30f, mx1 = -1e30f;
#pragma unroll
        for (int nc = 0; nc < 8; ++nc) {
            mx0 = fmaxf(mx0, fmaxf(c[nc][0], c[nc][1]));
            mx1 = fmaxf(mx1, fmaxf(c[nc][2], c[nc][3]));
        }
        mx0 = fmaxf(mx0, __shfl_xor_sync(0xffffffffu, mx0, 1));
        mx0 = fmaxf(mx0, __shfl_xor_sync(0xffffffffu, mx0, 2));
        mx1 = fmaxf(mx1, __shfl_xor_sync(0xffffffffu, mx1, 1));
        mx1 = fmaxf(mx1, __shfl_xor_sync(0xffffffffu, mx1, 2));

        float mn0 = fmaxf(m0, mx0), mn1 = fmaxf(m1, mx1);
        float cr0 = __expf(m0 - mn0), cr1 = __expf(m1 - mn1);
        m0 = mn0; m1 = mn1;

        float ps0 = 0.f, ps1 = 0.f;
#pragma unroll
        for (int nc = 0; nc < 8; ++nc) {
            c[nc][0] = __expf(c[nc][0] - mn0);
            c[nc][1] = __expf(c[nc][1] - mn0);
            c[nc][2] = __expf(c[nc][2] - mn1);
            c[nc][3] = __expf(c[nc][3] - mn1);
            ps0 += c[nc][0] + c[nc][1];
            ps1 += c[nc][2] + c[nc][3];
        }
        ps0 += __shfl_xor_sync(0xffffffffu, ps0, 1);
        ps0 += __shfl_xor_sync(0xffffffffu, ps0, 2);
        ps1 += __shfl_xor_sync(0xffffffffu, ps1, 1);
        ps1 += __shfl_xor_sync(0xffffffffu, ps1, 2);
        l0 = l0 * cr0 + ps0;
        l1 = l1 * cr1 + ps1;

#pragma unroll
        for (int nc = 0; nc < 8; ++nc) {
            acc[nc][0] *= cr0; acc[nc][1] *= cr0;
            acc[nc][2] *= cr1; acc[nc][3] *= cr1;
        }

#pragma unroll
        for (int nc = 0; nc < 8; ++nc)
#pragma unroll
            for (int i = 0; i < 4; ++i)
                c[nc][i] = __uint_as_float(f2tf32(c[nc][i]));

        const int srcA = (lane & 28) | (tig >> 1);
        const int srcB = srcA | 2;
        const bool odd = tig & 1;
#pragma unroll
        for (int kc = 0; kc < 8; ++kc) {
            float x0 = __shfl_sync(0xffffffffu, c[kc][0], srcA);
            float x1 = __shfl_sync(0xffffffffu, c[kc][1], srcA);
            float x2 = __shfl_sync(0xffffffffu, c[kc][2], srcA);
            float x3 = __shfl_sync(0xffffffffu, c[kc][3], srcA);
            float y0 = __shfl_sync(0xffffffffu, c[kc][0], srcB);
            float y1 = __shfl_sync(0xffffffffu, c[kc][1], srcB);
            float y2 = __shfl_sync(0xffffffffu, c[kc][2], srcB);
            float y3 = __shfl_sync(0xffffffffu, c[kc][3], srcB);
            uint32_t p0 = __float_as_uint(odd ? x1 : x0);
            uint32_t p1 = __float_as_uint(odd ? x3 : x2);
            uint32_t p2 = __float_as_uint(odd ? y1 : y0);
            uint32_t p3 = __float_as_uint(odd ? y3 : y2);
#pragma unroll
            for (int nc = 0; nc < 8; ++nc) {
                const float* vp = bV + (8 * kc + tig) * VP + 8 * nc + g;
                uint32_t b0 = __float_as_uint(vp[0]);
                uint32_t b1 = __float_as_uint(vp[4 * VP]);
                mma_tf32(acc[nc], p0, p1, p2, p3, b0, b1);
            }
        }
        __syncthreads();
    }

    // write O (tf32-rounded: feeds Wp tensor-core GEMM)
    float il0 = 1.f / l0, il1 = 1.f / l1;
    int q0 = qb * BR + w * 16 + g;
    int q1 = q0 + 8;
    float* aoB = AO + (size_t)n * C * L + (size_t)h * 64 * L;
#pragma unroll
    for (int nc = 0; nc < 8; ++nc) {
        int d0 = 8 * nc + 2 * tig;
        aoB[(size_t)d0 * L + q0]       = f2tf32f(acc[nc][0] * il0);
        aoB[(size_t)(d0 + 1) * L + q0] = f2tf32f(acc[nc][1] * il0);
        aoB[(size_t)d0 * L + q1]       = f2tf32f(acc[nc][2] * il1);
        aoB[(size_t)(d0 + 1) * L + q1] = f2tf32f(acc[nc][3] * il1);
    }
}

// ---------------- launch ----------------
extern "C" void kernel_launch(void* const* d_in, const int* in_sizes, int n_in,
                              void* d_out, int out_size) {
    const float* x     = (const float*)d_in[0];
    const float* gamma = (const float*)d_in[1];
    const float* beta  = (const float*)d_in[2];
    const float* Wq    = (const float*)d_in[3];
    const float* Wk    = (const float*)d_in[4];
    const float* Wv    = (const float*)d_in[5];
    const float* Wp    = (const float*)d_in[6];
    const float* bp    = (const float*)d_in[7];
    float* out = (float*)d_out;

    void *p_xn, *p_q, *p_k, *p_v, *p_ao, *p_wr;
    cudaGetSymbolAddress(&p_xn, g_xn);
    cudaGetSymbolAddress(&p_q,  g_q);
    cudaGetSymbolAddress(&p_k,  g_k);
    cudaGetSymbolAddress(&p_v,  g_v);
    cudaGetSymbolAddress(&p_ao, g_ao);
    cudaGetSymbolAddress(&p_wr, g_wr);
    const float* wr = (const float*)p_wr;

    wround_kernel<<<dim3(C * C / (4 * 256), 4), 256>>>(Wq, Wk, Wv, Wp, (float*)p_wr);
    gn_kernel<<<NB * GROUPS, 256>>>(x, gamma, beta, (float*)p_xn);

    cudaFuncSetAttribute(proj_kernel, cudaFuncAttributeMaxDynamicSharedMemorySize, PROJ_SMEM);
    dim3 pg(L / 128, C / 128, NB);
    proj_kernel<<<pg, 256, PROJ_SMEM>>>(wr + 0 * C * C, (const float*)p_xn, (float*)p_q, nullptr, 0, 0.125f);
    proj_kernel<<<pg, 256, PROJ_SMEM>>>(wr + 1 * C * C, (const float*)p_xn, (float*)p_k, nullptr, 0, 1.0f);
    proj_kernel<<<pg, 256, PROJ_SMEM>>>(wr + 2 * C * C, (const float*)p_xn, (float*)p_v, nullptr, 0, 1.0f);

    int smem = BUF * 2 * (int)sizeof(float);
    cudaFuncSetAttribute(attn_kernel, cudaFuncAttributeMaxDynamicSharedMemorySize, smem);
    attn_kernel<<<dim3(L / BR, NB * HEADS), 256, smem>>>(
        (const float*)p_q, (const float*)p_k, (const float*)p_v, (float*)p_ao);

    proj_kernel<<<pg, 256, PROJ_SMEM>>>(wr + 3 * C * C, (const float*)p_ao, out, bp, 1, 0.f);
}

// round 6
// speedup vs baseline: 7.3442x; 1.7743x over previous
#include <cuda_runtime.h>
#include <cuda_fp16.h>
#include <cstdint>

#define NB     4
#define C      256
#define L      4096
#define GROUPS 32
#define CPG    8
#define HEADS  4
#define DH     64
#define EPS    1e-5f

// attention tiling (fp16)
#define BR 128
#define BC 64
#define NJB (L / BC)
#define NTILES (NB * HEADS * (L / BR))   // 512
#define AGRID  296                        // 2 full waves @ 2 CTA/SM on 148 SMs
#define KP2 72                            // K tile pitch in halves (144B rows)
#define VP2 72
#define KTILE_H (BC * KP2)                // 4608 halves
#define ABUF_H  (2 * KTILE_H)             // K+V per buffer, halves
#define ABUF_B  (ABUF_H * 2)              // bytes per buffer (18432)
#define ATTN_SMEM (2 * ABUF_B)

// projection tiling (tf32, unchanged mainloop)
#define PBK 32
#define XP  132
#define WP  36
#define XS_FLOATS (PBK * XP)
#define WS_FLOATS (128 * WP)
#define PROJ_SMEM ((2 * XS_FLOATS + 2 * WS_FLOATS) * 4)

// ---------------- scratch ----------------
__device__ float  g_xn[(size_t)NB * C * L];
__device__ __half g_qh[(size_t)NB * HEADS * L * DH];   // [n][h][l][d]
__device__ __half g_kh[(size_t)NB * HEADS * L * DH];   // [n][h][l][d]
__device__ __half g_vh[(size_t)NB * HEADS * L * DH];   // [n][h][d][l]  (transposed!)
__device__ float  g_ao[(size_t)NB * C * L];
__device__ float  g_wr[4 * C * C];

// ---------------- helpers ----------------
__device__ __forceinline__ uint32_t f2tf32(float x) {
    uint32_t u;
    asm("cvt.rna.tf32.f32 %0, %1;" : "=r"(u) : "f"(x));
    return u;
}
__device__ __forceinline__ float f2tf32f(float x) {
    return __uint_as_float(f2tf32(x));
}
__device__ __forceinline__ uint32_t smem_u32(const void* p) {
    return (uint32_t)__cvta_generic_to_shared(p);
}
__device__ __forceinline__ void cp16(uint32_t saddr, const void* g) {
    asm volatile("cp.async.cg.shared.global [%0], [%1], 16;" :: "r"(saddr), "l"(g));
}
__device__ __forceinline__ void cp_commit() {
    asm volatile("cp.async.commit_group;");
}
__device__ __forceinline__ void cp_wait1() {
    asm volatile("cp.async.wait_group 1;");
}
__device__ __forceinline__ void mma_tf32(float c[4],
                                         uint32_t a0, uint32_t a1, uint32_t a2, uint32_t a3,
                                         uint32_t b0, uint32_t b1) {
    asm volatile(
        "mma.sync.aligned.m16n8k8.row.col.f32.tf32.tf32.f32 "
        "{%0,%1,%2,%3},{%4,%5,%6,%7},{%8,%9},{%0,%1,%2,%3};"
        : "+f"(c[0]), "+f"(c[1]), "+f"(c[2]), "+f"(c[3])
        : "r"(a0), "r"(a1), "r"(a2), "r"(a3), "r"(b0), "r"(b1));
}
__device__ __forceinline__ void mma_f16(float c[4],
                                        uint32_t a0, uint32_t a1, uint32_t a2, uint32_t a3,
                                        uint32_t b0, uint32_t b1) {
    asm volatile(
        "mma.sync.aligned.m16n8k16.row.col.f32.f16.f16.f32 "
        "{%0,%1,%2,%3},{%4,%5,%6,%7},{%8,%9},{%0,%1,%2,%3};"
        : "+f"(c[0]), "+f"(c[1]), "+f"(c[2]), "+f"(c[3])
        : "r"(a0), "r"(a1), "r"(a2), "r"(a3), "r"(b0), "r"(b1));
}
__device__ __forceinline__ uint32_t packh2(float a, float b) {
    __half2 h = __floats2half2_rn(a, b);
    return *reinterpret_cast<uint32_t*>(&h);
}

// ---------------- weight pre-round (rna -> tf32) ----------------
__global__ __launch_bounds__(256) void wround_kernel(const float* __restrict__ w0,
                                                     const float* __restrict__ w1,
                                                     const float* __restrict__ w2,
                                                     const float* __restrict__ w3,
                                                     float* __restrict__ outw) {
    const float* srcs[4] = {w0, w1, w2, w3};
    int m = blockIdx.y;
    const float4* s = (const float4*)srcs[m];
    float4* d = (float4*)(outw + (size_t)m * C * C);
    int i = blockIdx.x * 256 + threadIdx.x;
    float4 v = s[i];
    v.x = f2tf32f(v.x); v.y = f2tf32f(v.y);
    v.z = f2tf32f(v.z); v.w = f2tf32f(v.w);
    d[i] = v;
}

// ---------------- GroupNorm (output rounded to tf32) ----------------
__global__ __launch_bounds__(256) void gn_kernel(const float* __restrict__ x,
                                                 const float* __restrict__ gamma,
                                                 const float* __restrict__ beta,
                                                 float* __restrict__ xn) {
    int n = blockIdx.x >> 5, g = blockIdx.x & 31;
    size_t base = ((size_t)n * C + g * CPG) * L;
    const float4* xp = (const float4*)(x + base);
    float s = 0.f, ss = 0.f;
    const int NV = CPG * L / 4;
    for (int i = threadIdx.x; i < NV; i += 256) {
        float4 v = xp[i];
        s  += v.x + v.y + v.z + v.w;
        ss += v.x*v.x + v.y*v.y + v.z*v.z + v.w*v.w;
    }
    __shared__ float rs[256], rq[256];
    rs[threadIdx.x] = s; rq[threadIdx.x] = ss;
    __syncthreads();
    for (int off = 128; off; off >>= 1) {
        if (threadIdx.x < off) {
            rs[threadIdx.x] += rs[threadIdx.x + off];
            rq[threadIdx.x] += rq[threadIdx.x + off];
        }
        __syncthreads();
    }
    float mean = rs[0] * (1.f / (CPG * L));
    float var  = rq[0] * (1.f / (CPG * L)) - mean * mean;
    float inv  = rsqrtf(var + EPS);
    float4* op = (float4*)(xn + base);
    for (int i = threadIdx.x; i < NV; i += 256) {
        int c = g * CPG + (i >> 10);
        float gm = gamma[c] * inv;
        float bt = beta[c] - mean * gm;
        float4 v = xp[i];
        float4 o;
        o.x = f2tf32f(v.x * gm + bt); o.y = f2tf32f(v.y * gm + bt);
        o.z = f2tf32f(v.z * gm + bt); o.w = f2tf32f(v.w * gm + bt);
        op[i] = o;
    }
}

// ---------------- tf32 tensor-core 1x1-conv GEMM ----------------
// mode 0: Q/K fp16 [n][h][l][d] * oscale
// mode 2: V  fp16 transposed [n][h][d][l]
// mode 1: fp32 [n][c][l] + bias
__global__ __launch_bounds__(256, 2) void proj_kernel(const float* __restrict__ Wm,
                                                      const float* __restrict__ X,
                                                      void* __restrict__ outv,
                                                      const float* __restrict__ bias,
                                                      int mode, float oscale) {
    extern __shared__ float psm[];
    float* Xs = psm;
    float* Ws = psm + 2 * XS_FLOATS;
    const uint32_t xbase = smem_u32(Xs);
    const uint32_t wbase = smem_u32(Ws);

    const int tid  = threadIdx.x;
    const int lane = tid & 31;
    const int w    = tid >> 5;
    const int g    = lane >> 2;
    const int tig  = lane & 3;
    const int mwarp = (w >> 2) * 64;
    const int nwarp = (w & 3) * 32;

    const int n     = blockIdx.z;
    const int lbase = blockIdx.x * 128;
    const int obase = blockIdx.y * 128;
    const float* Xn = X + (size_t)n * C * L;

    float acc[4][4][4] = {};

    auto stage = [&](int s, int buf) {
        int cb = s * PBK;
        uint32_t xb = xbase + (uint32_t)(buf * XS_FLOATS) * 4u;
        uint32_t wb = wbase + (uint32_t)(buf * WS_FLOATS) * 4u;
#pragma unroll
        for (int it = 0; it < 4; ++it) {
            int i = tid + it * 256;
            int c = i >> 5, l4 = (i & 31) * 4;
            cp16(xb + (uint32_t)(c * XP + l4) * 4u,
                 Xn + (size_t)(cb + c) * L + lbase + l4);
        }
#pragma unroll
        for (int it = 0; it < 4; ++it) {
            int i = tid + it * 256;
            int o = i >> 3, c4 = (i & 7) * 4;
            cp16(wb + (uint32_t)(o * WP + c4) * 4u,
                 Wm + (size_t)(obase + o) * C + cb + c4);
        }
    };

    stage(0, 0);
    cp_commit();

    const int NSTG = C / PBK;
    for (int s = 0; s < NSTG; ++s) {
        if (s + 1 < NSTG) stage(s + 1, (s + 1) & 1);
        cp_commit();
        cp_wait1();
        __syncthreads();

        const float* bX = Xs + (s & 1) * XS_FLOATS;
        const float* bW = Ws + (s & 1) * WS_FLOATS;

#pragma unroll
        for (int kc = 0; kc < PBK; kc += 8) {
            uint32_t bf[4][2];
#pragma unroll
            for (int ni = 0; ni < 4; ++ni) {
                const float* wp = bW + (nwarp + ni * 8 + g) * WP + kc + tig;
                bf[ni][0] = __float_as_uint(wp[0]);
                bf[ni][1] = __float_as_uint(wp[4]);
            }
#pragma unroll
            for (int mi = 0; mi < 4; ++mi) {
                const float* xr0 = bX + (kc + tig) * XP + mwarp + mi * 16;
                const float* xr1 = bX + (kc + tig + 4) * XP + mwarp + mi * 16;
                uint32_t a0 = __float_as_uint(xr0[g]);
                uint32_t a1 = __float_as_uint(xr0[g + 8]);
                uint32_t a2 = __float_as_uint(xr1[g]);
                uint32_t a3 = __float_as_uint(xr1[g + 8]);
#pragma unroll
                for (int ni = 0; ni < 4; ++ni)
                    mma_tf32(acc[mi][ni], a0, a1, a2, a3, bf[ni][0], bf[ni][1]);
            }
        }
        __syncthreads();
    }

    if (mode == 0) {
        __half* outh = (__half*)outv;
#pragma unroll
        for (int mi = 0; mi < 4; ++mi) {
            int l0 = lbase + mwarp + mi * 16 + g;
#pragma unroll
            for (int ni = 0; ni < 4; ++ni) {
                int o = obase + nwarp + ni * 8 + 2 * tig;
                int h = o >> 6, d = o & 63;
                __half* op = outh + ((size_t)(n * HEADS + h) * L) * DH + d;
                __half2 v0 = __floats2half2_rn(acc[mi][ni][0] * oscale, acc[mi][ni][1] * oscale);
                __half2 v1 = __floats2half2_rn(acc[mi][ni][2] * oscale, acc[mi][ni][3] * oscale);
                *(__half2*)(op + (size_t)l0 * DH)       = v0;
                *(__half2*)(op + (size_t)(l0 + 8) * DH) = v1;
            }
        }
    } else if (mode == 2) {
        __half* outh = (__half*)outv;
#pragma unroll
        for (int mi = 0; mi < 4; ++mi) {
            int l0 = lbase + mwarp + mi * 16 + g;
#pragma unroll
            for (int ni = 0; ni < 4; ++ni) {
                int o = obase + nwarp + ni * 8 + 2 * tig;
                int h = o >> 6, d = o & 63;
                __half* op = outh + ((size_t)(n * HEADS + h) * DH + d) * L;
                op[l0]         = __float2half_rn(acc[mi][ni][0]);
                op[L + l0]     = __float2half_rn(acc[mi][ni][1]);
                op[l0 + 8]     = __float2half_rn(acc[mi][ni][2]);
                op[L + l0 + 8] = __float2half_rn(acc[mi][ni][3]);
            }
        }
    } else {
        float* out = (float*)outv;
#pragma unroll
        for (int mi = 0; mi < 4; ++mi) {
            int l0 = lbase + mwarp + mi * 16 + g;
#pragma unroll
            for (int ni = 0; ni < 4; ++ni) {
                int o = obase + nwarp + ni * 8 + 2 * tig;
                float b0 = bias[o], b1 = bias[o + 1];
                float* op = out + (size_t)n * C * L;
                op[(size_t)o * L + l0]             = acc[mi][ni][0] + b0;
                op[(size_t)(o + 1) * L + l0]       = acc[mi][ni][1] + b1;
                op[(size_t)o * L + l0 + 8]         = acc[mi][ni][2] + b0;
                op[(size_t)(o + 1) * L + l0 + 8]   = acc[mi][ni][3] + b1;
            }
        }
    }
}

// ---------------- fp16 tensor-core flash attention (persistent) ----------------
// tile t -> (qb = t & 31, nh = t >> 5); block = 8 warps, warp w: q-rows [16w,16w+16)
__global__ __launch_bounds__(256, 2) void attn_kernel(const __half* __restrict__ Q,
                                                      const __half* __restrict__ K,
                                                      const __half* __restrict__ V,
                                                      float* __restrict__ AO) {
    extern __shared__ __half smh[];
    const uint32_t sbase = smem_u32(smh);

    const int tid  = threadIdx.x;
    const int lane = tid & 31;
    const int w    = tid >> 5;
    const int g    = lane >> 2;
    const int tig  = lane & 3;

    for (int t = blockIdx.x; t < NTILES; t += AGRID) {
        const int qb = t & 31;
        const int nh = t >> 5;
        const int n  = nh >> 2, h = nh & 3;

        const uint32_t* Qu = (const uint32_t*)(Q + (size_t)nh * L * DH
                                               + ((size_t)qb * BR + w * 16) * DH);
        const __half* Kg = K + (size_t)nh * L * DH;    // [l][d]
        const __half* Vg = V + (size_t)nh * DH * L;    // [d][l]

        // Q A-fragments: a0..a3 per kc; u32 = half2 at (row, d-pair)
        uint32_t aq[4][4];
#pragma unroll
        for (int kc = 0; kc < 4; ++kc) {
            int b = g * 32 + 8 * kc + tig;
            aq[kc][0] = Qu[b];
            aq[kc][1] = Qu[b + 256];        // row g+8
            aq[kc][2] = Qu[b + 4];          // d+8
            aq[kc][3] = Qu[b + 260];
        }

        float m0 = -1e30f, m1 = -1e30f, l0 = 0.f, l1 = 0.f;
        float acc[8][4] = {};

        auto stage = [&](int jb, int buf) {
            uint32_t kb = sbase + (uint32_t)buf * ABUF_B;
            uint32_t vb = kb + KTILE_H * 2;
            const __half* Ks = Kg + (size_t)jb * BC * DH;      // 64 rows x 128B
            const __half* Vs = Vg + (size_t)jb * BC;           // 64 rows (d) x 128B @ stride L
#pragma unroll
            for (int it = 0; it < 2; ++it) {
                int i = tid + it * 256;                        // 512 chunks
                int j = i >> 3, dq = i & 7;
                cp16(kb + (uint32_t)(j * 144 + dq * 16), Ks + (size_t)j * DH + dq * 8);
            }
#pragma unroll
            for (int it = 0; it < 2; ++it) {
                int i = tid + it * 256;
                int j = i >> 3, dq = i & 7;
                cp16(vb + (uint32_t)(j * 144 + dq * 16), Vs + (size_t)j * L + dq * 8);
            }
        };

        stage(0, 0);
        cp_commit();

        for (int jb = 0; jb < NJB; ++jb) {
            if (jb + 1 < NJB) stage(jb + 1, (jb + 1) & 1);
            cp_commit();
            cp_wait1();
            __syncthreads();

            const uint32_t* bKu = (const uint32_t*)(smh + (jb & 1) * ABUF_H);
            const uint32_t* bVu = bKu + KTILE_H / 2;

            // ---- S = Q K^T (1/8 folded into Q) ----
            float c[8][4] = {};
#pragma unroll
            for (int kc = 0; kc < 4; ++kc) {
#pragma unroll
                for (int nc = 0; nc < 8; ++nc) {
                    int bi = (8 * nc + g) * 36 + 8 * kc + tig;
                    mma_f16(c[nc], aq[kc][0], aq[kc][1], aq[kc][2], aq[kc][3],
                            bKu[bi], bKu[bi + 4]);
                }
            }

            // ---- online softmax (registers + quad shuffles) ----
            float mx0 = -1e30f, mx1 = -1e30f;
#pragma unroll
            for (int nc = 0; nc < 8; ++nc) {
                mx0 = fmaxf(mx0, fmaxf(c[nc][0], c[nc][1]));
                mx1 = fmaxf(mx1, fmaxf(c[nc][2], c[nc][3]));
            }
            mx0 = fmaxf(mx0, __shfl_xor_sync(0xffffffffu, mx0, 1));
            mx0 = fmaxf(mx0, __shfl_xor_sync(0xffffffffu, mx0, 2));
            mx1 = fmaxf(mx1, __shfl_xor_sync(0xffffffffu, mx1, 1));
            mx1 = fmaxf(mx1, __shfl_xor_sync(0xffffffffu, mx1, 2));

            float mn0 = fmaxf(m0, mx0), mn1 = fmaxf(m1, mx1);
            float cr0 = __expf(m0 - mn0), cr1 = __expf(m1 - mn1);
            m0 = mn0; m1 = mn1;

            float ps0 = 0.f, ps1 = 0.f;
#pragma unroll
            for (int nc = 0; nc < 8; ++nc) {
                c[nc][0] = __expf(c[nc][0] - mn0);
                c[nc][1] = __expf(c[nc][1] - mn0);
                c[nc][2] = __expf(c[nc][2] - mn1);
                c[nc][3] = __expf(c[nc][3] - mn1);
                ps0 += c[nc][0] + c[nc][1];
                ps1 += c[nc][2] + c[nc][3];
            }
            ps0 += __shfl_xor_sync(0xffffffffu, ps0, 1);
            ps0 += __shfl_xor_sync(0xffffffffu, ps0, 2);
            ps1 += __shfl_xor_sync(0xffffffffu, ps1, 1);
            ps1 += __shfl_xor_sync(0xffffffffu, ps1, 2);
            l0 = l0 * cr0 + ps0;
            l1 = l1 * cr1 + ps1;

#pragma unroll
            for (int nc = 0; nc < 8; ++nc) {
                acc[nc][0] *= cr0; acc[nc][1] *= cr0;
                acc[nc][2] *= cr1; acc[nc][3] *= cr1;
            }

            // P: C-frag -> fp16 A-frag (layout identity, no shuffles)
            uint32_t ph[8][2];
#pragma unroll
            for (int nc = 0; nc < 8; ++nc) {
                ph[nc][0] = packh2(c[nc][0], c[nc][1]);   // row g
                ph[nc][1] = packh2(c[nc][2], c[nc][3]);   // row g+8
            }

            // ---- O += P V ----
#pragma unroll
            for (int kc = 0; kc < 4; ++kc) {
                uint32_t a0 = ph[2 * kc][0];
                uint32_t a1 = ph[2 * kc][1];
                uint32_t a2 = ph[2 * kc + 1][0];
                uint32_t a3 = ph[2 * kc + 1][1];
#pragma unroll
                for (int nc = 0; nc < 8; ++nc) {
                    int bi = (8 * nc + g) * 36 + 8 * kc + tig;
                    mma_f16(acc[nc], a0, a1, a2, a3, bVu[bi], bVu[bi + 4]);
                }
            }
            __syncthreads();
        }

        // write O (tf32-rounded: feeds Wp tensor-core GEMM), layout [n][c][l]
        float il0 = 1.f / l0, il1 = 1.f / l1;
        int q0 = qb * BR + w * 16 + g;
        int q1 = q0 + 8;
        float* aoB = AO + (size_t)n * C * L + (size_t)h * 64 * L;
#pragma unroll
        for (int nc = 0; nc < 8; ++nc) {
            int d0 = 8 * nc + 2 * tig;
            aoB[(size_t)d0 * L + q0]       = f2tf32f(acc[nc][0] * il0);
            aoB[(size_t)(d0 + 1) * L + q0] = f2tf32f(acc[nc][1] * il0);
            aoB[(size_t)d0 * L + q1]       = f2tf32f(acc[nc][2] * il1);
            aoB[(size_t)(d0 + 1) * L + q1] = f2tf32f(acc[nc][3] * il1);
        }
        __syncthreads();
    }
}

// ---------------- launch ----------------
extern "C" void kernel_launch(void* const* d_in, const int* in_sizes, int n_in,
                              void* d_out, int out_size) {
    const float* x     = (const float*)d_in[0];
    const float* gamma = (const float*)d_in[1];
    const float* beta  = (const float*)d_in[2];
    const float* Wq    = (const float*)d_in[3];
    const float* Wk    = (const float*)d_in[4];
    const float* Wv    = (const float*)d_in[5];
    const float* Wp    = (const float*)d_in[6];
    const float* bp    = (const float*)d_in[7];
    float* out = (float*)d_out;

    void *p_xn, *p_q, *p_k, *p_v, *p_ao, *p_wr;
    cudaGetSymbolAddress(&p_xn, g_xn);
    cudaGetSymbolAddress(&p_q,  g_qh);
    cudaGetSymbolAddress(&p_k,  g_kh);
    cudaGetSymbolAddress(&p_v,  g_vh);
    cudaGetSymbolAddress(&p_ao, g_ao);
    cudaGetSymbolAddress(&p_wr, g_wr);
    const float* wr = (const float*)p_wr;

    wround_kernel<<<dim3(C * C / (4 * 256), 4), 256>>>(Wq, Wk, Wv, Wp, (float*)p_wr);
    gn_kernel<<<NB * GROUPS, 256>>>(x, gamma, beta, (float*)p_xn);

    cudaFuncSetAttribute(proj_kernel, cudaFuncAttributeMaxDynamicSharedMemorySize, PROJ_SMEM);
    dim3 pg(L / 128, C / 128, NB);
    proj_kernel<<<pg, 256, PROJ_SMEM>>>(wr + 0 * C * C, (const float*)p_xn, p_q, nullptr, 0, 0.125f);
    proj_kernel<<<pg, 256, PROJ_SMEM>>>(wr + 1 * C * C, (const float*)p_xn, p_k, nullptr, 0, 1.0f);
    proj_kernel<<<pg, 256, PROJ_SMEM>>>(wr + 2 * C * C, (const float*)p_xn, p_v, nullptr, 2, 1.0f);

    cudaFuncSetAttribute(attn_kernel, cudaFuncAttributeMaxDynamicSharedMemorySize, ATTN_SMEM);
    attn_kernel<<<AGRID, 256, ATTN_SMEM>>>(
        (const __half*)p_q, (const __half*)p_k, (const __half*)p_v, (float*)p_ao);

    proj_kernel<<<pg, 256, PROJ_SMEM>>>(wr + 3 * C * C, (const float*)p_ao, out, bp, 1, 0.f);
}

// round 7
// speedup vs baseline: 8.1922x; 1.1155x over previous
#include <cuda_runtime.h>
#include <cuda_fp16.h>
#include <cstdint>

#define NB     4
#define C      256
#define L      4096
#define GROUPS 32
#define CPG    8
#define HEADS  4
#define DH     64
#define EPS    1e-5f

// attention tiling (fp16)
#define BR 128
#define BC 64
#define NJB (L / BC)
#define NTILES (NB * HEADS * (L / BR))   // 512
#define AGRID  296
#define KP2 72
#define KTILE_H (BC * KP2)
#define ABUF_H  (2 * KTILE_H)
#define ABUF_B  (ABUF_H * 2)
#define ATTN_SMEM (2 * ABUF_B)

// projection tiling (fp16)
#define PBK 32                   // c per stage
#define XPH 136                  // X smem pitch (halves): [c][l]
#define WPH 40                   // W smem pitch (halves): [o][c]
#define XS_H (PBK * XPH)         // 4352 halves / buffer
#define WS_H (128 * WPH)         // 5120 halves / buffer
#define PROJ_SMEM ((2 * XS_H + 2 * WS_H) * 2)   // 37888 B

// ---------------- scratch ----------------
__device__ __half g_xnh[(size_t)NB * C * L];           // groupnormed x, fp16 [c][l]
__device__ __half g_qh[(size_t)NB * HEADS * L * DH];   // [n][h][l][d]
__device__ __half g_kh[(size_t)NB * HEADS * L * DH];   // [n][h][l][d]
__device__ __half g_vh[(size_t)NB * HEADS * L * DH];   // [n][h][d][l]
__device__ __half g_aoh[(size_t)NB * C * L];           // attention out fp16 [c][l]
__device__ __half g_wh[4 * C * C];                     // fp16 Wq,Wk,Wv,Wp
__device__ float2 g_st[NB * GROUPS];                   // groupnorm {mean, inv}

// ---------------- helpers ----------------
__device__ __forceinline__ uint32_t smem_u32(const void* p) {
    return (uint32_t)__cvta_generic_to_shared(p);
}
__device__ __forceinline__ void cp16(uint32_t saddr, const void* g) {
    asm volatile("cp.async.cg.shared.global [%0], [%1], 16;" :: "r"(saddr), "l"(g));
}
__device__ __forceinline__ void cp_commit() {
    asm volatile("cp.async.commit_group;");
}
__device__ __forceinline__ void cp_wait1() {
    asm volatile("cp.async.wait_group 1;");
}
__device__ __forceinline__ void mma_f16(float c[4],
                                        uint32_t a0, uint32_t a1, uint32_t a2, uint32_t a3,
                                        uint32_t b0, uint32_t b1) {
    asm volatile(
        "mma.sync.aligned.m16n8k16.row.col.f32.f16.f16.f32 "
        "{%0,%1,%2,%3},{%4,%5,%6,%7},{%8,%9},{%0,%1,%2,%3};"
        : "+f"(c[0]), "+f"(c[1]), "+f"(c[2]), "+f"(c[3])
        : "r"(a0), "r"(a1), "r"(a2), "r"(a3), "r"(b0), "r"(b1));
}
__device__ __forceinline__ void ldsm4t(uint32_t& r0, uint32_t& r1, uint32_t& r2, uint32_t& r3,
                                       uint32_t addr) {
    asm volatile("ldmatrix.sync.aligned.m8n8.x4.trans.shared.b16 {%0,%1,%2,%3}, [%4];"
                 : "=r"(r0), "=r"(r1), "=r"(r2), "=r"(r3) : "r"(addr));
}
__device__ __forceinline__ uint32_t packh2(float a, float b) {
    __half2 h = __floats2half2_rn(a, b);
    return *reinterpret_cast<uint32_t*>(&h);
}

// ---------------- weight convert fp32 -> fp16 ----------------
__global__ __launch_bounds__(256) void wconv_kernel(const float* __restrict__ w0,
                                                    const float* __restrict__ w1,
                                                    const float* __restrict__ w2,
                                                    const float* __restrict__ w3,
                                                    __half* __restrict__ outw) {
    const float* srcs[4] = {w0, w1, w2, w3};
    int m = blockIdx.y;
    const float4* s = (const float4*)srcs[m];
    int i = blockIdx.x * 256 + threadIdx.x;   // C*C/4 float4s
    float4 v = s[i];
    __half2 h0 = __floats2half2_rn(v.x, v.y);
    __half2 h1 = __floats2half2_rn(v.z, v.w);
    uint2 p = make_uint2(*(uint32_t*)&h0, *(uint32_t*)&h1);
    ((uint2*)(outw + (size_t)m * C * C))[i] = p;
}

// ---------------- GroupNorm: stats then apply ----------------
__global__ __launch_bounds__(256) void gn_stats(const float* __restrict__ x,
                                                float2* __restrict__ st) {
    int n = blockIdx.x >> 5, g = blockIdx.x & 31;
    size_t base = ((size_t)n * C + g * CPG) * L;
    const float4* xp = (const float4*)(x + base);
    float s = 0.f, ss = 0.f;
    const int NV = CPG * L / 4;
    for (int i = threadIdx.x; i < NV; i += 256) {
        float4 v = xp[i];
        s  += v.x + v.y + v.z + v.w;
        ss += v.x*v.x + v.y*v.y + v.z*v.z + v.w*v.w;
    }
    __shared__ float rs[256], rq[256];
    rs[threadIdx.x] = s; rq[threadIdx.x] = ss;
    __syncthreads();
    for (int off = 128; off; off >>= 1) {
        if (threadIdx.x < off) {
            rs[threadIdx.x] += rs[threadIdx.x + off];
            rq[threadIdx.x] += rq[threadIdx.x + off];
        }
        __syncthreads();
    }
    if (threadIdx.x == 0) {
        float mean = rs[0] * (1.f / (CPG * L));
        float var  = rq[0] * (1.f / (CPG * L)) - mean * mean;
        st[blockIdx.x] = make_float2(mean, rsqrtf(var + EPS));
    }
}

__global__ __launch_bounds__(256) void gn_apply(const float* __restrict__ x,
                                                const float* __restrict__ gamma,
                                                const float* __restrict__ beta,
                                                const float2* __restrict__ st,
                                                __half* __restrict__ xn) {
    size_t base = ((size_t)blockIdx.x * 256 + threadIdx.x) * 8;
    int n = (int)(base >> 20);                 // C*L = 2^20
    int c = (int)((base >> 12) & (C - 1));     // L = 2^12
    float2 mv = st[n * GROUPS + (c >> 3)];
    float gm = gamma[c] * mv.y;
    float bt = beta[c] - mv.x * gm;
    const float4* xp = (const float4*)(x + base);
    float4 a = xp[0], b = xp[1];
    __half2 h0 = __floats2half2_rn(a.x * gm + bt, a.y * gm + bt);
    __half2 h1 = __floats2half2_rn(a.z * gm + bt, a.w * gm + bt);
    __half2 h2 = __floats2half2_rn(b.x * gm + bt, b.y * gm + bt);
    __half2 h3 = __floats2half2_rn(b.z * gm + bt, b.w * gm + bt);
    uint4 p = make_uint4(*(uint32_t*)&h0, *(uint32_t*)&h1, *(uint32_t*)&h2, *(uint32_t*)&h3);
    *(uint4*)(xn + base) = p;
}

// ---------------- fp16 tensor-core 1x1-conv GEMM ----------------
// out[o,l] = sum_c W[o,c] X[c,l]; A = X^T via ldmatrix.trans, B = W
// grid (L/128, C/128, NB), 8 warps (2m x 4n); warp tile 64 l x 32 o
// mode 0: Q/K fp16 [n][h][l][d]*oscale ; mode 2: V fp16 [n][h][d][l] ; mode 1: fp32 [c][l]+bias
__global__ __launch_bounds__(256, 2) void proj_kernel(const __half* __restrict__ Wm,
                                                      const __half* __restrict__ X,
                                                      void* __restrict__ outv,
                                                      const float* __restrict__ bias,
                                                      int mode, float oscale) {
    extern __shared__ __half psm[];
    __half* Xs = psm;                 // 2 x [PBK][XPH]
    __half* Ws = psm + 2 * XS_H;      // 2 x [128][WPH]
    const uint32_t xbase = smem_u32(Xs);
    const uint32_t wbase = smem_u32(Ws);

    const int tid  = threadIdx.x;
    const int lane = tid & 31;
    const int w    = tid >> 5;
    const int g    = lane >> 2;
    const int tig  = lane & 3;
    const int mwarp = (w >> 2) * 64;
    const int nwarp = (w & 3) * 32;

    const int n     = blockIdx.z;
    const int lbase = blockIdx.x * 128;
    const int obase = blockIdx.y * 128;
    const __half* Xn = X + (size_t)n * C * L;

    // ldmatrix lane address components: tile t = lane>>3, row r = lane&7
    const int lt = lane >> 3, lr = lane & 7;
    const int k_add = (lt >> 1) * 8 + lr;        // k row within 16-chunk
    const int m_add = (lt & 1) * 8;              // m col offset within 16-tile

    float acc[4][4][4] = {};

    auto stage = [&](int s, int buf) {
        int cb = s * PBK;
        uint32_t xb = xbase + (uint32_t)(buf * XS_H) * 2u;
        uint32_t wb = wbase + (uint32_t)(buf * WS_H) * 2u;
        // X tile: 32c x 128l halves = 512 16B chunks
#pragma unroll
        for (int it = 0; it < 2; ++it) {
            int i = tid + it * 256;
            int c = i >> 4, l8 = (i & 15) * 8;
            cp16(xb + (uint32_t)(c * XPH + l8) * 2u,
                 Xn + (size_t)(cb + c) * L + lbase + l8);
        }
        // W tile: 128o x 32c halves = 512 chunks
#pragma unroll
        for (int it = 0; it < 2; ++it) {
            int i = tid + it * 256;
            int o = i >> 2, c8 = (i & 3) * 8;
            cp16(wb + (uint32_t)(o * WPH + c8) * 2u,
                 Wm + (size_t)(obase + o) * C + cb + c8);
        }
    };

    stage(0, 0);
    cp_commit();

    const int NSTG = C / PBK;  // 8
    for (int s = 0; s < NSTG; ++s) {
        if (s + 1 < NSTG) stage(s + 1, (s + 1) & 1);
        cp_commit();
        cp_wait1();
        __syncthreads();

        uint32_t xbuf = xbase + (uint32_t)((s & 1) * XS_H) * 2u;
        const uint32_t* Wu = (const uint32_t*)(Ws + (s & 1) * WS_H);

#pragma unroll
        for (int kc = 0; kc < 2; ++kc) {       // PBK/16
            // B-frags from W [o][c]
            uint32_t bf[4][2];
#pragma unroll
            for (int ni = 0; ni < 4; ++ni) {
                int bi = (nwarp + ni * 8 + g) * (WPH / 2) + kc * 8 + tig;
                bf[ni][0] = Wu[bi];
                bf[ni][1] = Wu[bi + 4];
            }
            // A-frags from X [c][l] via ldmatrix.x4.trans
#pragma unroll
            for (int mi = 0; mi < 4; ++mi) {
                uint32_t addr = xbuf +
                    (uint32_t)((kc * 16 + k_add) * XPH + mwarp + mi * 16 + m_add) * 2u;
                uint32_t a0, a1, a2, a3;
                ldsm4t(a0, a1, a2, a3, addr);
#pragma unroll
                for (int ni = 0; ni < 4; ++ni)
                    mma_f16(acc[mi][ni], a0, a1, a2, a3, bf[ni][0], bf[ni][1]);
            }
        }
        __syncthreads();
    }

    if (mode == 0) {
        __half* outh = (__half*)outv;
#pragma unroll
        for (int mi = 0; mi < 4; ++mi) {
            int l0 = lbase + mwarp + mi * 16 + g;
#pragma unroll
            for (int ni = 0; ni < 4; ++ni) {
                int o = obase + nwarp + ni * 8 + 2 * tig;
                int h = o >> 6, d = o & 63;
                __half* op = outh + ((size_t)(n * HEADS + h) * L) * DH + d;
                __half2 v0 = __floats2half2_rn(acc[mi][ni][0] * oscale, acc[mi][ni][1] * oscale);
                __half2 v1 = __floats2half2_rn(acc[mi][ni][2] * oscale, acc[mi][ni][3] * oscale);
                *(__half2*)(op + (size_t)l0 * DH)       = v0;
                *(__half2*)(op + (size_t)(l0 + 8) * DH) = v1;
            }
        }
    } else if (mode == 2) {
        __half* outh = (__half*)outv;
#pragma unroll
        for (int mi = 0; mi < 4; ++mi) {
            int l0 = lbase + mwarp + mi * 16 + g;
#pragma unroll
            for (int ni = 0; ni < 4; ++ni) {
                int o = obase + nwarp + ni * 8 + 2 * tig;
                int h = o >> 6, d = o & 63;
                __half* op = outh + ((size_t)(n * HEADS + h) * DH + d) * L;
                op[l0]         = __float2half_rn(acc[mi][ni][0]);
                op[L + l0]     = __float2half_rn(acc[mi][ni][1]);
                op[l0 + 8]     = __float2half_rn(acc[mi][ni][2]);
                op[L + l0 + 8] = __float2half_rn(acc[mi][ni][3]);
            }
        }
    } else {
        float* out = (float*)outv;
#pragma unroll
        for (int mi = 0; mi < 4; ++mi) {
            int l0 = lbase + mwarp + mi * 16 + g;
#pragma unroll
            for (int ni = 0; ni < 4; ++ni) {
                int o = obase + nwarp + ni * 8 + 2 * tig;
                float b0 = bias[o], b1 = bias[o + 1];
                float* op = out + (size_t)n * C * L;
                op[(size_t)o * L + l0]             = acc[mi][ni][0] + b0;
                op[(size_t)(o + 1) * L + l0]       = acc[mi][ni][1] + b1;
                op[(size_t)o * L + l0 + 8]         = acc[mi][ni][2] + b0;
                op[(size_t)(o + 1) * L + l0 + 8]   = acc[mi][ni][3] + b1;
            }
        }
    }
}

// ---------------- fp16 tensor-core flash attention (persistent) ----------------
__global__ __launch_bounds__(256, 2) void attn_kernel(const __half* __restrict__ Q,
                                                      const __half* __restrict__ K,
                                                      const __half* __restrict__ V,
                                                      __half* __restrict__ AO) {
    extern __shared__ __half smh[];
    const uint32_t sbase = smem_u32(smh);

    const int tid  = threadIdx.x;
    const int lane = tid & 31;
    const int w    = tid >> 5;
    const int g    = lane >> 2;
    const int tig  = lane & 3;

    for (int t = blockIdx.x; t < NTILES; t += AGRID) {
        const int qb = t & 31;
        const int nh = t >> 5;
        const int n  = nh >> 2, h = nh & 3;

        const uint32_t* Qu = (const uint32_t*)(Q + (size_t)nh * L * DH
                                               + ((size_t)qb * BR + w * 16) * DH);
        const __half* Kg = K + (size_t)nh * L * DH;
        const __half* Vg = V + (size_t)nh * DH * L;

        uint32_t aq[4][4];
#pragma unroll
        for (int kc = 0; kc < 4; ++kc) {
            int b = g * 32 + 8 * kc + tig;
            aq[kc][0] = Qu[b];
            aq[kc][1] = Qu[b + 256];
            aq[kc][2] = Qu[b + 4];
            aq[kc][3] = Qu[b + 260];
        }

        float m0 = -1e30f, m1 = -1e30f, l0 = 0.f, l1 = 0.f;
        float acc[8][4] = {};

        auto stage = [&](int jb, int buf) {
            uint32_t kb = sbase + (uint32_t)buf * ABUF_B;
            uint32_t vb = kb + KTILE_H * 2;
            const __half* Ks = Kg + (size_t)jb * BC * DH;
            const __half* Vs = Vg + (size_t)jb * BC;
#pragma unroll
            for (int it = 0; it < 2; ++it) {
                int i = tid + it * 256;
                int j = i >> 3, dq = i & 7;
                cp16(kb + (uint32_t)(j * 144 + dq * 16), Ks + (size_t)j * DH + dq * 8);
            }
#pragma unroll
            for (int it = 0; it < 2; ++it) {
                int i = tid + it * 256;
                int j = i >> 3, dq = i & 7;
                cp16(vb + (uint32_t)(j * 144 + dq * 16), Vs + (size_t)j * L + dq * 8);
            }
        };

        stage(0, 0);
        cp_commit();

        for (int jb = 0; jb < NJB; ++jb) {
            if (jb + 1 < NJB) stage(jb + 1, (jb + 1) & 1);
            cp_commit();
            cp_wait1();
            __syncthreads();

            const uint32_t* bKu = (const uint32_t*)(smh + (jb & 1) * ABUF_H);
            const uint32_t* bVu = bKu + KTILE_H / 2;

            float c[8][4] = {};
#pragma unroll
            for (int kc = 0; kc < 4; ++kc) {
#pragma unroll
                for (int nc = 0; nc < 8; ++nc) {
                    int bi = (8 * nc + g) * 36 + 8 * kc + tig;
                    mma_f16(c[nc], aq[kc][0], aq[kc][1], aq[kc][2], aq[kc][3],
                            bKu[bi], bKu[bi + 4]);
                }
            }

            float mx0 = -1e30f, mx1 = -1e30f;
#pragma unroll
            for (int nc = 0; nc < 8; ++nc) {
                mx0 = fmaxf(mx0, fmaxf(c[nc][0], c[nc][1]));
                mx1 = fmaxf(mx1, fmaxf(c[nc][2], c[nc][3]));
            }
            mx0 = fmaxf(mx0, __shfl_xor_sync(0xffffffffu, mx0, 1));
            mx0 = fmaxf(mx0, __shfl_xor_sync(0xffffffffu, mx0, 2));
            mx1 = fmaxf(mx1, __shfl_xor_sync(0xffffffffu, mx1, 1));
            mx1 = fmaxf(mx1, __shfl_xor_sync(0xffffffffu, mx1, 2));

            float mn0 = fmaxf(m0, mx0), mn1 = fmaxf(m1, mx1);
            float cr0 = __expf(m0 - mn0), cr1 = __expf(m1 - mn1);
            m0 = mn0; m1 = mn1;

            float ps0 = 0.f, ps1 = 0.f;
#pragma unroll
            for (int nc = 0; nc < 8; ++nc) {
                c[nc][0] = __expf(c[nc][0] - mn0);
                c[nc][1] = __expf(c[nc][1] - mn0);
                c[nc][2] = __expf(c[nc][2] - mn1);
                c[nc][3] = __expf(c[nc][3] - mn1);
                ps0 += c[nc][0] + c[nc][1];
                ps1 += c[nc][2] + c[nc][3];
            }
            ps0 += __shfl_xor_sync(0xffffffffu, ps0, 1);
            ps0 += __shfl_xor_sync(0xffffffffu, ps0, 2);
            ps1 += __shfl_xor_sync(0xffffffffu, ps1, 1);
            ps1 += __shfl_xor_sync(0xffffffffu, ps1, 2);
            l0 = l0 * cr0 + ps0;
            l1 = l1 * cr1 + ps1;

#pragma unroll
            for (int nc = 0; nc < 8; ++nc) {
                acc[nc][0] *= cr0; acc[nc][1] *= cr0;
                acc[nc][2] *= cr1; acc[nc][3] *= cr1;
            }

            uint32_t ph[8][2];
#pragma unroll
            for (int nc = 0; nc < 8; ++nc) {
                ph[nc][0] = packh2(c[nc][0], c[nc][1]);
                ph[nc][1] = packh2(c[nc][2], c[nc][3]);
            }

#pragma unroll
            for (int kc = 0; kc < 4; ++kc) {
                uint32_t a0 = ph[2 * kc][0];
                uint32_t a1 = ph[2 * kc][1];
                uint32_t a2 = ph[2 * kc + 1][0];
                uint32_t a3 = ph[2 * kc + 1][1];
#pragma unroll
                for (int nc = 0; nc < 8; ++nc) {
                    int bi = (8 * nc + g) * 36 + 8 * kc + tig;
                    mma_f16(acc[nc], a0, a1, a2, a3, bVu[bi], bVu[bi + 4]);
                }
            }
            __syncthreads();
        }

        // write O as fp16 [n][c][l] (feeds fp16 Wp GEMM)
        float il0 = 1.f / l0, il1 = 1.f / l1;
        int q0 = qb * BR + w * 16 + g;
        int q1 = q0 + 8;
        __half* aoB = AO + (size_t)n * C * L + (size_t)h * 64 * L;
#pragma unroll
        for (int nc = 0; nc < 8; ++nc) {
            int d0 = 8 * nc + 2 * tig;
            aoB[(size_t)d0 * L + q0]       = __float2half_rn(acc[nc][0] * il0);
            aoB[(size_t)(d0 + 1) * L + q0] = __float2half_rn(acc[nc][1] * il0);
            aoB[(size_t)d0 * L + q1]       = __float2half_rn(acc[nc][2] * il1);
            aoB[(size_t)(d0 + 1) * L + q1] = __float2half_rn(acc[nc][3] * il1);
        }
        __syncthreads();
    }
}

// ---------------- launch ----------------
extern "C" void kernel_launch(void* const* d_in, const int* in_sizes, int n_in,
                              void* d_out, int out_size) {
    const float* x     = (const float*)d_in[0];
    const float* gamma = (const float*)d_in[1];
    const float* beta  = (const float*)d_in[2];
    const float* Wq    = (const float*)d_in[3];
    const float* Wk    = (const float*)d_in[4];
    const float* Wv    = (const float*)d_in[5];
    const float* Wp    = (const float*)d_in[6];
    const float* bp    = (const float*)d_in[7];
    float* out = (float*)d_out;

    void *p_xn, *p_q, *p_k, *p_v, *p_ao, *p_wh, *p_st;
    cudaGetSymbolAddress(&p_xn, g_xnh);
    cudaGetSymbolAddress(&p_q,  g_qh);
    cudaGetSymbolAddress(&p_k,  g_kh);
    cudaGetSymbolAddress(&p_v,  g_vh);
    cudaGetSymbolAddress(&p_ao, g_aoh);
    cudaGetSymbolAddress(&p_wh, g_wh);
    cudaGetSymbolAddress(&p_st, g_st);
    const __half* wh = (const __half*)p_wh;

    wconv_kernel<<<dim3(C * C / (4 * 256), 4), 256>>>(Wq, Wk, Wv, Wp, (__half*)p_wh);
    gn_stats<<<NB * GROUPS, 256>>>(x, (float2*)p_st);
    gn_apply<<<(int)((size_t)NB * C * L / (256 * 8)), 256>>>(
        x, gamma, beta, (const float2*)p_st, (__half*)p_xn);

    cudaFuncSetAttribute(proj_kernel, cudaFuncAttributeMaxDynamicSharedMemorySize, PROJ_SMEM);
    dim3 pg(L / 128, C / 128, NB);
    proj_kernel<<<pg, 256, PROJ_SMEM>>>(wh + 0 * C * C, (const __half*)p_xn, p_q, nullptr, 0, 0.125f);
    proj_kernel<<<pg, 256, PROJ_SMEM>>>(wh + 1 * C * C, (const __half*)p_xn, p_k, nullptr, 0, 1.0f);
    proj_kernel<<<pg, 256, PROJ_SMEM>>>(wh + 2 * C * C, (const __half*)p_xn, p_v, nullptr, 2, 1.0f);

    cudaFuncSetAttribute(attn_kernel, cudaFuncAttributeMaxDynamicSharedMemorySize, ATTN_SMEM);
    attn_kernel<<<AGRID, 256, ATTN_SMEM>>>(
        (const __half*)p_q, (const __half*)p_k, (const __half*)p_v, (__half*)p_ao);

    proj_kernel<<<pg, 256, PROJ_SMEM>>>(wh + 3 * C * C, (const __half*)p_ao, out, bp, 1, 0.f);
}

// round 9
// speedup vs baseline: 8.3638x; 1.0209x over previous
#include <cuda_runtime.h>
#include <cuda_fp16.h>
#include <cstdint>

#define NB     4
#define C      256
#define L      4096
#define GROUPS 32
#define CPG    8
#define HEADS  4
#define DH     64
#define EPS    1e-5f

// attention tiling (fp16 mma.sync)
#define BR 128
#define BC 64
#define NJB (L / BC)
#define NTILES (NB * HEADS * (L / BR))   // 512
#define AGRID  296
#define KP2 72
#define KTILE_H (BC * KP2)
#define ABUF_H  (2 * KTILE_H)
#define ABUF_B  (ABUF_H * 2)
#define ATTN_SMEM (2 * ABUF_B)

// projection tiling (fp16)
#define PBK 32
#define XPH 136
#define WPH 40
#define XS_H (PBK * XPH)
#define WS_H (128 * WPH)
#define PROJ_SMEM ((2 * XS_H + 2 * WS_H) * 2)

#define QSCALE 0.180336880f     // 0.125 * log2(e) : softmax done in exp2 domain

// ---------------- scratch ----------------
__device__ __half g_xnh[(size_t)NB * C * L];
__device__ __half g_qh[(size_t)NB * HEADS * L * DH];   // [n][h][l][d]
__device__ __half g_kh[(size_t)NB * HEADS * L * DH];   // [n][h][l][d]
__device__ __half g_vh[(size_t)NB * HEADS * L * DH];   // [n][h][d][l]
__device__ __half g_aoh[(size_t)NB * C * L];
__device__ __half g_wh[4 * C * C];
__device__ float2 g_st[NB * GROUPS];

// ---------------- helpers ----------------
__device__ __forceinline__ uint32_t smem_u32(const void* p) {
    return (uint32_t)__cvta_generic_to_shared(p);
}
__device__ __forceinline__ void cp16(uint32_t saddr, const void* g) {
    asm volatile("cp.async.cg.shared.global [%0], [%1], 16;" :: "r"(saddr), "l"(g));
}
__device__ __forceinline__ void cp_commit() { asm volatile("cp.async.commit_group;"); }
__device__ __forceinline__ void cp_wait1()  { asm volatile("cp.async.wait_group 1;"); }
__device__ __forceinline__ void mma_f16(float c[4],
                                        uint32_t a0, uint32_t a1, uint32_t a2, uint32_t a3,
                                        uint32_t b0, uint32_t b1) {
    asm volatile(
        "mma.sync.aligned.m16n8k16.row.col.f32.f16.f16.f32 "
        "{%0,%1,%2,%3},{%4,%5,%6,%7},{%8,%9},{%0,%1,%2,%3};"
        : "+f"(c[0]), "+f"(c[1]), "+f"(c[2]), "+f"(c[3])
        : "r"(a0), "r"(a1), "r"(a2), "r"(a3), "r"(b0), "r"(b1));
}
__device__ __forceinline__ void ldsm4t(uint32_t& r0, uint32_t& r1, uint32_t& r2, uint32_t& r3,
                                       uint32_t addr) {
    asm volatile("ldmatrix.sync.aligned.m8n8.x4.trans.shared.b16 {%0,%1,%2,%3}, [%4];"
                 : "=r"(r0), "=r"(r1), "=r"(r2), "=r"(r3) : "r"(addr));
}
__device__ __forceinline__ uint32_t packh2(float a, float b) {
    __half2 h = __floats2half2_rn(a, b);
    return *reinterpret_cast<uint32_t*>(&h);
}
__device__ __forceinline__ float ex2f(float x) {
    float r;
    asm("ex2.approx.f32 %0, %1;" : "=f"(r) : "f"(x));
    return r;
}

// ---------------- weight convert fp32 -> fp16 ----------------
__global__ __launch_bounds__(256) void wconv_kernel(const float* __restrict__ w0,
                                                    const float* __restrict__ w1,
                                                    const float* __restrict__ w2,
                                                    const float* __restrict__ w3,
                                                    __half* __restrict__ outw) {
    const float* srcs[4] = {w0, w1, w2, w3};
    int m = blockIdx.y;
    const float4* s = (const float4*)srcs[m];
    int i = blockIdx.x * 256 + threadIdx.x;
    float4 v = s[i];
    __half2 h0 = __floats2half2_rn(v.x, v.y);
    __half2 h1 = __floats2half2_rn(v.z, v.w);
    uint2 p = make_uint2(*(uint32_t*)&h0, *(uint32_t*)&h1);
    ((uint2*)(outw + (size_t)m * C * C))[i] = p;
}

// ---------------- GroupNorm ----------------
__global__ __launch_bounds__(256) void gn_stats(const float* __restrict__ x,
                                                float2* __restrict__ st) {
    int n = blockIdx.x >> 5, g = blockIdx.x & 31;
    size_t base = ((size_t)n * C + g * CPG) * L;
    const float4* xp = (const float4*)(x + base);
    float s = 0.f, ss = 0.f;
    const int NV = CPG * L / 4;
    for (int i = threadIdx.x; i < NV; i += 256) {
        float4 v = xp[i];
        s  += v.x + v.y + v.z + v.w;
        ss += v.x*v.x + v.y*v.y + v.z*v.z + v.w*v.w;
    }
    __shared__ float rs[256], rq[256];
    rs[threadIdx.x] = s; rq[threadIdx.x] = ss;
    __syncthreads();
    for (int off = 128; off; off >>= 1) {
        if (threadIdx.x < off) {
            rs[threadIdx.x] += rs[threadIdx.x + off];
            rq[threadIdx.x] += rq[threadIdx.x + off];
        }
        __syncthreads();
    }
    if (threadIdx.x == 0) {
        float mean = rs[0] * (1.f / (CPG * L));
        float var  = rq[0] * (1.f / (CPG * L)) - mean * mean;
        st[blockIdx.x] = make_float2(mean, rsqrtf(var + EPS));
    }
}

__global__ __launch_bounds__(256) void gn_apply(const float* __restrict__ x,
                                                const float* __restrict__ gamma,
                                                const float* __restrict__ beta,
                                                const float2* __restrict__ st,
                                                __half* __restrict__ xn) {
    size_t base = ((size_t)blockIdx.x * 256 + threadIdx.x) * 8;
    int n = (int)(base >> 20);
    int c = (int)((base >> 12) & (C - 1));
    float2 mv = st[n * GROUPS + (c >> 3)];
    float gm = gamma[c] * mv.y;
    float bt = beta[c] - mv.x * gm;
    const float4* xp = (const float4*)(x + base);
    float4 a = xp[0], b = xp[1];
    __half2 h0 = __floats2half2_rn(a.x * gm + bt, a.y * gm + bt);
    __half2 h1 = __floats2half2_rn(a.z * gm + bt, a.w * gm + bt);
    __half2 h2 = __floats2half2_rn(b.x * gm + bt, b.y * gm + bt);
    __half2 h3 = __floats2half2_rn(b.z * gm + bt, b.w * gm + bt);
    uint4 p = make_uint4(*(uint32_t*)&h0, *(uint32_t*)&h1, *(uint32_t*)&h2, *(uint32_t*)&h3);
    *(uint4*)(xn + base) = p;
}

// ---------------- shared GEMM mainloop (device inline) ----------------
// computes acc[4][4][4] for one 128l x 128o tile at (n, lbase, obase) with weights Wm
__device__ __forceinline__ void gemm_tile(const __half* __restrict__ Wm,
                                          const __half* __restrict__ Xn,
                                          int lbase, int obase,
                                          __half* psm, float acc[4][4][4]) {
    __half* Xs = psm;
    __half* Ws = psm + 2 * XS_H;
    const uint32_t xbase = smem_u32(Xs);
    const uint32_t wbase = smem_u32(Ws);

    const int tid  = threadIdx.x;
    const int lane = tid & 31;
    const int w    = tid >> 5;
    const int g    = lane >> 2;
    const int tig  = lane & 3;
    const int mwarp = (w >> 2) * 64;
    const int nwarp = (w & 3) * 32;

    const int lt = lane >> 3, lr = lane & 7;
    const int k_add = (lt >> 1) * 8 + lr;
    const int m_add = (lt & 1) * 8;

    auto stage = [&](int s, int buf) {
        int cb = s * PBK;
        uint32_t xb = xbase + (uint32_t)(buf * XS_H) * 2u;
        uint32_t wb = wbase + (uint32_t)(buf * WS_H) * 2u;
#pragma unroll
        for (int it = 0; it < 2; ++it) {
            int i = tid + it * 256;
            int c = i >> 4, l8 = (i & 15) * 8;
            cp16(xb + (uint32_t)(c * XPH + l8) * 2u,
                 Xn + (size_t)(cb + c) * L + lbase + l8);
        }
#pragma unroll
        for (int it = 0; it < 2; ++it) {
            int i = tid + it * 256;
            int o = i >> 2, c8 = (i & 3) * 8;
            cp16(wb + (uint32_t)(o * WPH + c8) * 2u,
                 Wm + (size_t)(obase + o) * C + cb + c8);
        }
    };

    stage(0, 0);
    cp_commit();

    const int NSTG = C / PBK;
    for (int s = 0; s < NSTG; ++s) {
        if (s + 1 < NSTG) stage(s + 1, (s + 1) & 1);
        cp_commit();
        cp_wait1();
        __syncthreads();

        uint32_t xbuf = xbase + (uint32_t)((s & 1) * XS_H) * 2u;
        const uint32_t* Wu = (const uint32_t*)(Ws + (s & 1) * WS_H);

#pragma unroll
        for (int kc = 0; kc < 2; ++kc) {
            uint32_t bf[4][2];
#pragma unroll
            for (int ni = 0; ni < 4; ++ni) {
                int bi = (nwarp + ni * 8 + g) * (WPH / 2) + kc * 8 + tig;
                bf[ni][0] = Wu[bi];
                bf[ni][1] = Wu[bi + 4];
            }
#pragma unroll
            for (int mi = 0; mi < 4; ++mi) {
                uint32_t addr = xbuf +
                    (uint32_t)((kc * 16 + k_add) * XPH + mwarp + mi * 16 + m_add) * 2u;
                uint32_t a0, a1, a2, a3;
                ldsm4t(a0, a1, a2, a3, addr);
#pragma unroll
                for (int ni = 0; ni < 4; ++ni)
                    mma_f16(acc[mi][ni], a0, a1, a2, a3, bf[ni][0], bf[ni][1]);
            }
        }
        __syncthreads();
    }
}

// ---------------- fused QKV projection ----------------
// grid (L/128, 6, NB): blockIdx.y -> (wsel = y>>1 in {Q,K,V}, obase = (y&1)*128)
__global__ __launch_bounds__(256, 2) void qkv_kernel(const __half* __restrict__ Wh,
                                                     const __half* __restrict__ X,
                                                     __half* __restrict__ Qo,
                                                     __half* __restrict__ Ko,
                                                     __half* __restrict__ Vo) {
    extern __shared__ __half psm[];
    const int wsel  = blockIdx.y >> 1;
    const int obase = (blockIdx.y & 1) * 128;
    const int n     = blockIdx.z;
    const int lbase = blockIdx.x * 128;
    const __half* Xn = X + (size_t)n * C * L;
    const __half* Wm = Wh + (size_t)wsel * C * C;

    float acc[4][4][4] = {};
    gemm_tile(Wm, Xn, lbase, obase, psm, acc);

    const int tid  = threadIdx.x;
    const int lane = tid & 31;
    const int w    = tid >> 5;
    const int g    = lane >> 2;
    const int tig  = lane & 3;
    const int mwarp = (w >> 2) * 64;
    const int nwarp = (w & 3) * 32;

    if (wsel < 2) {
        // Q (scaled by 1/8*log2e) or K: fp16 [n][h][l][d]
        float oscale = (wsel == 0) ? QSCALE : 1.0f;
        __half* outh = (wsel == 0) ? Qo : Ko;
#pragma unroll
        for (int mi = 0; mi < 4; ++mi) {
            int l0 = lbase + mwarp + mi * 16 + g;
#pragma unroll
            for (int ni = 0; ni < 4; ++ni) {
                int o = obase + nwarp + ni * 8 + 2 * tig;
                int h = o >> 6, d = o & 63;
                __half* op = outh + ((size_t)(n * HEADS + h) * L) * DH + d;
                __half2 v0 = __floats2half2_rn(acc[mi][ni][0] * oscale, acc[mi][ni][1] * oscale);
                __half2 v1 = __floats2half2_rn(acc[mi][ni][2] * oscale, acc[mi][ni][3] * oscale);
                *(__half2*)(op + (size_t)l0 * DH)       = v0;
                *(__half2*)(op + (size_t)(l0 + 8) * DH) = v1;
            }
        }
    } else {
        // V: fp16 transposed [n][h][d][l]
#pragma unroll
        for (int mi = 0; mi < 4; ++mi) {
            int l0 = lbase + mwarp + mi * 16 + g;
#pragma unroll
            for (int ni = 0; ni < 4; ++ni) {
                int o = obase + nwarp + ni * 8 + 2 * tig;
                int h = o >> 6, d = o & 63;
                __half* op = Vo + ((size_t)(n * HEADS + h) * DH + d) * L;
                op[l0]         = __float2half_rn(acc[mi][ni][0]);
                op[L + l0]     = __float2half_rn(acc[mi][ni][1]);
                op[l0 + 8]     = __float2half_rn(acc[mi][ni][2]);
                op[L + l0 + 8] = __float2half_rn(acc[mi][ni][3]);
            }
        }
    }
}

// ---------------- final projection (Wp, fp32 out + bias) ----------------
__global__ __launch_bounds__(256, 2) void projp_kernel(const __half* __restrict__ Wm,
                                                       const __half* __restrict__ X,
                                                       float* __restrict__ out,
                                                       const float* __restrict__ bias) {
    extern __shared__ __half psm[];
    const int n     = blockIdx.z;
    const int lbase = blockIdx.x * 128;
    const int obase = blockIdx.y * 128;
    const __half* Xn = X + (size_t)n * C * L;

    float acc[4][4][4] = {};
    gemm_tile(Wm, Xn, lbase, obase, psm, acc);

    const int tid  = threadIdx.x;
    const int lane = tid & 31;
    const int w    = tid >> 5;
    const int g    = lane >> 2;
    const int tig  = lane & 3;
    const int mwarp = (w >> 2) * 64;
    const int nwarp = (w & 3) * 32;

#pragma unroll
    for (int mi = 0; mi < 4; ++mi) {
        int l0 = lbase + mwarp + mi * 16 + g;
#pragma unroll
        for (int ni = 0; ni < 4; ++ni) {
            int o = obase + nwarp + ni * 8 + 2 * tig;
            float b0 = bias[o], b1 = bias[o + 1];
            float* op = out + (size_t)n * C * L;
            op[(size_t)o * L + l0]             = acc[mi][ni][0] + b0;
            op[(size_t)(o + 1) * L + l0]       = acc[mi][ni][1] + b1;
            op[(size_t)o * L + l0 + 8]         = acc[mi][ni][2] + b0;
            op[(size_t)(o + 1) * L + l0 + 8]   = acc[mi][ni][3] + b1;
        }
    }
}

// ---------------- fp16 tensor-core flash attention (persistent, exp2 domain) ----------------
__global__ __launch_bounds__(256, 2) void attn_kernel(const __half* __restrict__ Q,
                                                      const __half* __restrict__ K,
                                                      const __half* __restrict__ V,
                                                      __half* __restrict__ AO) {
    extern __shared__ __half smh[];
    const uint32_t sbase = smem_u32(smh);

    const int tid  = threadIdx.x;
    const int lane = tid & 31;
    const int w    = tid >> 5;
    const int g    = lane >> 2;
    const int tig  = lane & 3;

    for (int t = blockIdx.x; t < NTILES; t += AGRID) {
        const int qb = t & 31;
        const int nh = t >> 5;
        const int n  = nh >> 2, h = nh & 3;

        const uint32_t* Qu = (const uint32_t*)(Q + (size_t)nh * L * DH
                                               + ((size_t)qb * BR + w * 16) * DH);
        const __half* Kg = K + (size_t)nh * L * DH;
        const __half* Vg = V + (size_t)nh * DH * L;

        uint32_t aq[4][4];
#pragma unroll
        for (int kc = 0; kc < 4; ++kc) {
            int b = g * 32 + 8 * kc + tig;
            aq[kc][0] = Qu[b];
            aq[kc][1] = Qu[b + 256];
            aq[kc][2] = Qu[b + 4];
            aq[kc][3] = Qu[b + 260];
        }

        float m0 = -1e30f, m1 = -1e30f, l0 = 0.f, l1 = 0.f;
        float acc[8][4] = {};

        auto stage = [&](int jb, int buf) {
            uint32_t kb = sbase + (uint32_t)buf * ABUF_B;
            uint32_t vb = kb + KTILE_H * 2;
            const __half* Ks = Kg + (size_t)jb * BC * DH;
            const __half* Vs = Vg + (size_t)jb * BC;
#pragma unroll
            for (int it = 0; it < 2; ++it) {
                int i = tid + it * 256;
                int j = i >> 3, dq = i & 7;
                cp16(kb + (uint32_t)(j * 144 + dq * 16), Ks + (size_t)j * DH + dq * 8);
            }
#pragma unroll
            for (int it = 0; it < 2; ++it) {
                int i = tid + it * 256;
                int j = i >> 3, dq = i & 7;
                cp16(vb + (uint32_t)(j * 144 + dq * 16), Vs + (size_t)j * L + dq * 8);
            }
        };

        stage(0, 0);
        cp_commit();

        for (int jb = 0; jb < NJB; ++jb) {
            if (jb + 1 < NJB) stage(jb + 1, (jb + 1) & 1);
            cp_commit();
            cp_wait1();
            __syncthreads();

            const uint32_t* bKu = (const uint32_t*)(smh + (jb & 1) * ABUF_H);
            const uint32_t* bVu = bKu + KTILE_H / 2;

            // S' = Q K^T, already in log2 units (log2e folded into Q scale)
            float c[8][4] = {};
#pragma unroll
            for (int kc = 0; kc < 4; ++kc) {
#pragma unroll
                for (int nc = 0; nc < 8; ++nc) {
                    int bi = (8 * nc + g) * 36 + 8 * kc + tig;
                    mma_f16(c[nc], aq[kc][0], aq[kc][1], aq[kc][2], aq[kc][3],
                            bKu[bi], bKu[bi + 4]);
                }
            }

            float mx0 = -1e30f, mx1 = -1e30f;
#pragma unroll
            for (int nc = 0; nc < 8; ++nc) {
                mx0 = fmaxf(mx0, fmaxf(c[nc][0], c[nc][1]));
                mx1 = fmaxf(mx1, fmaxf(c[nc][2], c[nc][3]));
            }
            mx0 = fmaxf(mx0, __shfl_xor_sync(0xffffffffu, mx0, 1));
            mx0 = fmaxf(mx0, __shfl_xor_sync(0xffffffffu, mx0, 2));
            mx1 = fmaxf(mx1, __shfl_xor_sync(0xffffffffu, mx1, 1));
            mx1 = fmaxf(mx1, __shfl_xor_sync(0xffffffffu, mx1, 2));

            float mn0 = fmaxf(m0, mx0), mn1 = fmaxf(m1, mx1);
            float cr0 = ex2f(m0 - mn0), cr1 = ex2f(m1 - mn1);
            m0 = mn0; m1 = mn1;

            float ps0 = 0.f, ps1 = 0.f;
#pragma unroll
            for (int nc = 0; nc < 8; ++nc) {
                c[nc][0] = ex2f(c[nc][0] - mn0);
                c[nc][1] = ex2f(c[nc][1] - mn0);
                c[nc][2] = ex2f(c[nc][2] - mn1);
                c[nc][3] = ex2f(c[nc][3] - mn1);
                ps0 += c[nc][0] + c[nc][1];
                ps1 += c[nc][2] + c[nc][3];
            }
            ps0 += __shfl_xor_sync(0xffffffffu, ps0, 1);
            ps0 += __shfl_xor_sync(0xffffffffu, ps0, 2);
            ps1 += __shfl_xor_sync(0xffffffffu, ps1, 1);
            ps1 += __shfl_xor_sync(0xffffffffu, ps1, 2);
            l0 = l0 * cr0 + ps0;
            l1 = l1 * cr1 + ps1;

#pragma unroll
            for (int nc = 0; nc < 8; ++nc) {
                acc[nc][0] *= cr0; acc[nc][1] *= cr0;
                acc[nc][2] *= cr1; acc[nc][3] *= cr1;
            }

            uint32_t ph[8][2];
#pragma unroll
            for (int nc = 0; nc < 8; ++nc) {
                ph[nc][0] = packh2(c[nc][0], c[nc][1]);
                ph[nc][1] = packh2(c[nc][2], c[nc][3]);
            }

#pragma unroll
            for (int kc = 0; kc < 4; ++kc) {
                uint32_t a0 = ph[2 * kc][0];
                uint32_t a1 = ph[2 * kc][1];
                uint32_t a2 = ph[2 * kc + 1][0];
                uint32_t a3 = ph[2 * kc + 1][1];
#pragma unroll
                for (int nc = 0; nc < 8; ++nc) {
                    int bi = (8 * nc + g) * 36 + 8 * kc + tig;
                    mma_f16(acc[nc], a0, a1, a2, a3, bVu[bi], bVu[bi + 4]);
                }
            }
            __syncthreads();
        }

        float il0 = 1.f / l0, il1 = 1.f / l1;
        int q0 = qb * BR + w * 16 + g;
        int q1 = q0 + 8;
        __half* aoB = AO + (size_t)n * C * L + (size_t)h * 64 * L;
#pragma unroll
        for (int nc = 0; nc < 8; ++nc) {
            int d0 = 8 * nc + 2 * tig;
            aoB[(size_t)d0 * L + q0]       = __float2half_rn(acc[nc][0] * il0);
            aoB[(size_t)(d0 + 1) * L + q0] = __float2half_rn(acc[nc][1] * il0);
            aoB[(size_t)d0 * L + q1]       = __float2half_rn(acc[nc][2] * il1);
            aoB[(size_t)(d0 + 1) * L + q1] = __float2half_rn(acc[nc][3] * il1);
        }
        __syncthreads();
    }
}

// ---------------- launch ----------------
extern "C" void kernel_launch(void* const* d_in, const int* in_sizes, int n_in,
                              void* d_out, int out_size) {
    const float* x     = (const float*)d_in[0];
    const float* gamma = (const float*)d_in[1];
    const float* beta  = (const float*)d_in[2];
    const float* Wq    = (const float*)d_in[3];
    const float* Wk    = (const float*)d_in[4];
    const float* Wv    = (const float*)d_in[5];
    const float* Wp    = (const float*)d_in[6];
    const float* bp    = (const float*)d_in[7];
    float* out = (float*)d_out;

    void *p_xn, *p_q, *p_k, *p_v, *p_ao, *p_wh, *p_st;
    cudaGetSymbolAddress(&p_xn, g_xnh);
    cudaGetSymbolAddress(&p_q,  g_qh);
    cudaGetSymbolAddress(&p_k,  g_kh);
    cudaGetSymbolAddress(&p_v,  g_vh);
    cudaGetSymbolAddress(&p_ao, g_aoh);
    cudaGetSymbolAddress(&p_wh, g_wh);
    cudaGetSymbolAddress(&p_st, g_st);
    const __half* wh = (const __half*)p_wh;

    wconv_kernel<<<dim3(C * C / (4 * 256), 4), 256>>>(Wq, Wk, Wv, Wp, (__half*)p_wh);
    gn_stats<<<NB * GROUPS, 256>>>(x, (float2*)p_st);
    gn_apply<<<(int)((size_t)NB * C * L / (256 * 8)), 256>>>(
        x, gamma, beta, (const float2*)p_st, (__half*)p_xn);

    cudaFuncSetAttribute(qkv_kernel, cudaFuncAttributeMaxDynamicSharedMemorySize, PROJ_SMEM);
    cudaFuncSetAttribute(projp_kernel, cudaFuncAttributeMaxDynamicSharedMemorySize, PROJ_SMEM);

    qkv_kernel<<<dim3(L / 128, 6, NB), 256, PROJ_SMEM>>>(
        wh, (const __half*)p_xn, (__half*)p_q, (__half*)p_k, (__half*)p_v);

    cudaFuncSetAttribute(attn_kernel, cudaFuncAttributeMaxDynamicSharedMemorySize, ATTN_SMEM);
    attn_kernel<<<AGRID, 256, ATTN_SMEM>>>(
        (const __half*)p_q, (const __half*)p_k, (const __half*)p_v, (__half*)p_ao);

    projp_kernel<<<dim3(L / 128, C / 128, NB), 256, PROJ_SMEM>>>(
        wh + 3 * C * C, (const __half*)p_ao, out, bp);
}

// round 10
// speedup vs baseline: 8.8872x; 1.0626x over previous
#include <cuda_runtime.h>
#include <cuda_fp16.h>
#include <cstdint>

#define NB     4
#define C      256
#define L      4096
#define GROUPS 32
#define CPG    8
#define HEADS  4
#define DH     64
#define EPS    1e-5f

// attention tiling (fp16 mma.sync)
#define BR 128
#define BC 64
#define NJB (L / BC)
#define NTILES (NB * HEADS * (L / BR))   // 512
#define AGRID  296
#define KP2 72
#define KTILE_H (BC * KP2)
#define ABUF_H  (2 * KTILE_H)
#define ABUF_B  (ABUF_H * 2)
#define ATTN_SMEM (2 * ABUF_B)

// projection tiling (fp16)
#define PBK 32
#define XPH 136
#define WPH 40
#define XS_H (PBK * XPH)
#define WS_H (128 * WPH)
#define PROJ_SMEM ((2 * XS_H + 2 * WS_H) * 2)

#define QSCALE 0.180336880f     // 0.125 * log2(e) : softmax done in exp2 domain

// ---------------- scratch ----------------
__device__ __half g_xnh[(size_t)NB * C * L];
__device__ __half g_qh[(size_t)NB * HEADS * L * DH];   // [n][h][l][d]
__device__ __half g_kh[(size_t)NB * HEADS * L * DH];   // [n][h][l][d]
__device__ __half g_vh[(size_t)NB * HEADS * L * DH];   // [n][h][d][l]
__device__ __half g_aoh[(size_t)NB * C * L];
__device__ __half g_wh[4 * C * C];
__device__ float2 g_st[NB * GROUPS];

// ---------------- helpers ----------------
__device__ __forceinline__ uint32_t smem_u32(const void* p) {
    return (uint32_t)__cvta_generic_to_shared(p);
}
__device__ __forceinline__ void cp16(uint32_t saddr, const void* g) {
    asm volatile("cp.async.cg.shared.global [%0], [%1], 16;" :: "r"(saddr), "l"(g));
}
__device__ __forceinline__ void cp_commit() { asm volatile("cp.async.commit_group;"); }
__device__ __forceinline__ void cp_wait1()  { asm volatile("cp.async.wait_group 1;"); }
__device__ __forceinline__ void mma_f16(float c[4],
                                        uint32_t a0, uint32_t a1, uint32_t a2, uint32_t a3,
                                        uint32_t b0, uint32_t b1) {
    asm volatile(
        "mma.sync.aligned.m16n8k16.row.col.f32.f16.f16.f32 "
        "{%0,%1,%2,%3},{%4,%5,%6,%7},{%8,%9},{%0,%1,%2,%3};"
        : "+f"(c[0]), "+f"(c[1]), "+f"(c[2]), "+f"(c[3])
        : "r"(a0), "r"(a1), "r"(a2), "r"(a3), "r"(b0), "r"(b1));
}
__device__ __forceinline__ void ldsm4t(uint32_t& r0, uint32_t& r1, uint32_t& r2, uint32_t& r3,
                                       uint32_t addr) {
    asm volatile("ldmatrix.sync.aligned.m8n8.x4.trans.shared.b16 {%0,%1,%2,%3}, [%4];"
                 : "=r"(r0), "=r"(r1), "=r"(r2), "=r"(r3) : "r"(addr));
}
__device__ __forceinline__ void ldsm4(uint32_t& r0, uint32_t& r1, uint32_t& r2, uint32_t& r3,
                                      uint32_t addr) {
    asm volatile("ldmatrix.sync.aligned.m8n8.x4.shared.b16 {%0,%1,%2,%3}, [%4];"
                 : "=r"(r0), "=r"(r1), "=r"(r2), "=r"(r3) : "r"(addr));
}
__device__ __forceinline__ uint32_t packh2(float a, float b) {
    __half2 h = __floats2half2_rn(a, b);
    return *reinterpret_cast<uint32_t*>(&h);
}
__device__ __forceinline__ float ex2f(float x) {
    float r;
    asm("ex2.approx.f32 %0, %1;" : "=f"(r) : "f"(x));
    return r;
}

// ---------------- weight convert fp32 -> fp16 ----------------
__global__ __launch_bounds__(256) void wconv_kernel(const float* __restrict__ w0,
                                                    const float* __restrict__ w1,
                                                    const float* __restrict__ w2,
                                                    const float* __restrict__ w3,
                                                    __half* __restrict__ outw) {
    const float* srcs[4] = {w0, w1, w2, w3};
    int m = blockIdx.y;
    const float4* s = (const float4*)srcs[m];
    int i = blockIdx.x * 256 + threadIdx.x;
    float4 v = s[i];
    __half2 h0 = __floats2half2_rn(v.x, v.y);
    __half2 h1 = __floats2half2_rn(v.z, v.w);
    uint2 p = make_uint2(*(uint32_t*)&h0, *(uint32_t*)&h1);
    ((uint2*)(outw + (size_t)m * C * C))[i] = p;
}

// ---------------- GroupNorm ----------------
__global__ __launch_bounds__(256) void gn_stats(const float* __restrict__ x,
                                                float2* __restrict__ st) {
    int n = blockIdx.x >> 5, g = blockIdx.x & 31;
    size_t base = ((size_t)n * C + g * CPG) * L;
    const float4* xp = (const float4*)(x + base);
    float s = 0.f, ss = 0.f;
    const int NV = CPG * L / 4;
    for (int i = threadIdx.x; i < NV; i += 256) {
        float4 v = xp[i];
        s  += v.x + v.y + v.z + v.w;
        ss += v.x*v.x + v.y*v.y + v.z*v.z + v.w*v.w;
    }
    __shared__ float rs[256], rq[256];
    rs[threadIdx.x] = s; rq[threadIdx.x] = ss;
    __syncthreads();
    for (int off = 128; off; off >>= 1) {
        if (threadIdx.x < off) {
            rs[threadIdx.x] += rs[threadIdx.x + off];
            rq[threadIdx.x] += rq[threadIdx.x + off];
        }
        __syncthreads();
    }
    if (threadIdx.x == 0) {
        float mean = rs[0] * (1.f / (CPG * L));
        float var  = rq[0] * (1.f / (CPG * L)) - mean * mean;
        st[blockIdx.x] = make_float2(mean, rsqrtf(var + EPS));
    }
}

__global__ __launch_bounds__(256) void gn_apply(const float* __restrict__ x,
                                                const float* __restrict__ gamma,
                                                const float* __restrict__ beta,
                                                const float2* __restrict__ st,
                                                __half* __restrict__ xn) {
    size_t base = ((size_t)blockIdx.x * 256 + threadIdx.x) * 8;
    int n = (int)(base >> 20);
    int c = (int)((base >> 12) & (C - 1));
    float2 mv = st[n * GROUPS + (c >> 3)];
    float gm = gamma[c] * mv.y;
    float bt = beta[c] - mv.x * gm;
    const float4* xp = (const float4*)(x + base);
    float4 a = xp[0], b = xp[1];
    __half2 h0 = __floats2half2_rn(a.x * gm + bt, a.y * gm + bt);
    __half2 h1 = __floats2half2_rn(a.z * gm + bt, a.w * gm + bt);
    __half2 h2 = __floats2half2_rn(b.x * gm + bt, b.y * gm + bt);
    __half2 h3 = __floats2half2_rn(b.z * gm + bt, b.w * gm + bt);
    uint4 p = make_uint4(*(uint32_t*)&h0, *(uint32_t*)&h1, *(uint32_t*)&h2, *(uint32_t*)&h3);
    *(uint4*)(xn + base) = p;
}

// ---------------- shared GEMM mainloop (device inline) ----------------
__device__ __forceinline__ void gemm_tile(const __half* __restrict__ Wm,
                                          const __half* __restrict__ Xn,
                                          int lbase, int obase,
                                          __half* psm, float acc[4][4][4]) {
    __half* Xs = psm;
    __half* Ws = psm + 2 * XS_H;
    const uint32_t xbase = smem_u32(Xs);
    const uint32_t wbase = smem_u32(Ws);

    const int tid  = threadIdx.x;
    const int lane = tid & 31;
    const int w    = tid >> 5;
    const int g    = lane >> 2;
    const int tig  = lane & 3;
    const int mwarp = (w >> 2) * 64;
    const int nwarp = (w & 3) * 32;

    const int lt = lane >> 3, lr = lane & 7;
    const int k_add = (lt >> 1) * 8 + lr;
    const int m_add = (lt & 1) * 8;

    auto stage = [&](int s, int buf) {
        int cb = s * PBK;
        uint32_t xb = xbase + (uint32_t)(buf * XS_H) * 2u;
        uint32_t wb = wbase + (uint32_t)(buf * WS_H) * 2u;
#pragma unroll
        for (int it = 0; it < 2; ++it) {
            int i = tid + it * 256;
            int c = i >> 4, l8 = (i & 15) * 8;
            cp16(xb + (uint32_t)(c * XPH + l8) * 2u,
                 Xn + (size_t)(cb + c) * L + lbase + l8);
        }
#pragma unroll
        for (int it = 0; it < 2; ++it) {
            int i = tid + it * 256;
            int o = i >> 2, c8 = (i & 3) * 8;
            cp16(wb + (uint32_t)(o * WPH + c8) * 2u,
                 Wm + (size_t)(obase + o) * C + cb + c8);
        }
    };

    stage(0, 0);
    cp_commit();

    const int NSTG = C / PBK;
    for (int s = 0; s < NSTG; ++s) {
        if (s + 1 < NSTG) stage(s + 1, (s + 1) & 1);
        cp_commit();
        cp_wait1();
        __syncthreads();

        uint32_t xbuf = xbase + (uint32_t)((s & 1) * XS_H) * 2u;
        const uint32_t* Wu = (const uint32_t*)(Ws + (s & 1) * WS_H);

#pragma unroll
        for (int kc = 0; kc < 2; ++kc) {
            uint32_t bf[4][2];
#pragma unroll
            for (int ni = 0; ni < 4; ++ni) {
                int bi = (nwarp + ni * 8 + g) * (WPH / 2) + kc * 8 + tig;
                bf[ni][0] = Wu[bi];
                bf[ni][1] = Wu[bi + 4];
            }
#pragma unroll
            for (int mi = 0; mi < 4; ++mi) {
                uint32_t addr = xbuf +
                    (uint32_t)((kc * 16 + k_add) * XPH + mwarp + mi * 16 + m_add) * 2u;
                uint32_t a0, a1, a2, a3;
                ldsm4t(a0, a1, a2, a3, addr);
#pragma unroll
                for (int ni = 0; ni < 4; ++ni)
                    mma_f16(acc[mi][ni], a0, a1, a2, a3, bf[ni][0], bf[ni][1]);
            }
        }
        __syncthreads();
    }
}

// ---------------- fused QKV projection ----------------
__global__ __launch_bounds__(256, 2) void qkv_kernel(const __half* __restrict__ Wh,
                                                     const __half* __restrict__ X,
                                                     __half* __restrict__ Qo,
                                                     __half* __restrict__ Ko,
                                                     __half* __restrict__ Vo) {
    extern __shared__ __half psm[];
    const int wsel  = blockIdx.y >> 1;
    const int obase = (blockIdx.y & 1) * 128;
    const int n     = blockIdx.z;
    const int lbase = blockIdx.x * 128;
    const __half* Xn = X + (size_t)n * C * L;
    const __half* Wm = Wh + (size_t)wsel * C * C;

    float acc[4][4][4] = {};
    gemm_tile(Wm, Xn, lbase, obase, psm, acc);

    const int tid  = threadIdx.x;
    const int lane = tid & 31;
    const int w    = tid >> 5;
    const int g    = lane >> 2;
    const int tig  = lane & 3;
    const int mwarp = (w >> 2) * 64;
    const int nwarp = (w & 3) * 32;

    if (wsel < 2) {
        float oscale = (wsel == 0) ? QSCALE : 1.0f;
        __half* outh = (wsel == 0) ? Qo : Ko;
#pragma unroll
        for (int mi = 0; mi < 4; ++mi) {
            int l0 = lbase + mwarp + mi * 16 + g;
#pragma unroll
            for (int ni = 0; ni < 4; ++ni) {
                int o = obase + nwarp + ni * 8 + 2 * tig;
                int h = o >> 6, d = o & 63;
                __half* op = outh + ((size_t)(n * HEADS + h) * L) * DH + d;
                __half2 v0 = __floats2half2_rn(acc[mi][ni][0] * oscale, acc[mi][ni][1] * oscale);
                __half2 v1 = __floats2half2_rn(acc[mi][ni][2] * oscale, acc[mi][ni][3] * oscale);
                *(__half2*)(op + (size_t)l0 * DH)       = v0;
                *(__half2*)(op + (size_t)(l0 + 8) * DH) = v1;
            }
        }
    } else {
#pragma unroll
        for (int mi = 0; mi < 4; ++mi) {
            int l0 = lbase + mwarp + mi * 16 + g;
#pragma unroll
            for (int ni = 0; ni < 4; ++ni) {
                int o = obase + nwarp + ni * 8 + 2 * tig;
                int h = o >> 6, d = o & 63;
                __half* op = Vo + ((size_t)(n * HEADS + h) * DH + d) * L;
                op[l0]         = __float2half_rn(acc[mi][ni][0]);
                op[L + l0]     = __float2half_rn(acc[mi][ni][1]);
                op[l0 + 8]     = __float2half_rn(acc[mi][ni][2]);
                op[L + l0 + 8] = __float2half_rn(acc[mi][ni][3]);
            }
        }
    }
}

// ---------------- final projection (Wp, fp32 out + bias) ----------------
__global__ __launch_bounds__(256, 2) void projp_kernel(const __half* __restrict__ Wm,
                                                       const __half* __restrict__ X,
                                                       float* __restrict__ out,
                                                       const float* __restrict__ bias) {
    extern __shared__ __half psm[];
    const int n     = blockIdx.z;
    const int lbase = blockIdx.x * 128;
    const int obase = blockIdx.y * 128;
    const __half* Xn = X + (size_t)n * C * L;

    float acc[4][4][4] = {};
    gemm_tile(Wm, Xn, lbase, obase, psm, acc);

    const int tid  = threadIdx.x;
    const int lane = tid & 31;
    const int w    = tid >> 5;
    const int g    = lane >> 2;
    const int tig  = lane & 3;
    const int mwarp = (w >> 2) * 64;
    const int nwarp = (w & 3) * 32;

#pragma unroll
    for (int mi = 0; mi < 4; ++mi) {
        int l0 = lbase + mwarp + mi * 16 + g;
#pragma unroll
        for (int ni = 0; ni < 4; ++ni) {
            int o = obase + nwarp + ni * 8 + 2 * tig;
            float b0 = bias[o], b1 = bias[o + 1];
            float* op = out + (size_t)n * C * L;
            op[(size_t)o * L + l0]             = acc[mi][ni][0] + b0;
            op[(size_t)(o + 1) * L + l0]       = acc[mi][ni][1] + b1;
            op[(size_t)o * L + l0 + 8]         = acc[mi][ni][2] + b0;
            op[(size_t)(o + 1) * L + l0 + 8]   = acc[mi][ni][3] + b1;
        }
    }
}

// ---------------- fp16 tensor-core flash attention (persistent, ldmatrix B) ----------------
__global__ __launch_bounds__(256, 2) void attn_kernel(const __half* __restrict__ Q,
                                                      const __half* __restrict__ K,
                                                      const __half* __restrict__ V,
                                                      __half* __restrict__ AO) {
    extern __shared__ __half smh[];
    const uint32_t sbase = smem_u32(smh);

    const int tid  = threadIdx.x;
    const int lane = tid & 31;
    const int w    = tid >> 5;
    const int g    = lane >> 2;
    const int tig  = lane & 3;

    // ldmatrix B-frag lane addressing:
    // lane groups 0-7/8-15/16-23/24-31 -> matrices m0..m3 of each x4:
    //   m0: rows r+0..7,  +0B   m1: rows r+0..7,  +16B
    //   m2: rows r+8..15, +0B   m3: rows r+8..15, +16B
    const uint32_t lrow  = (uint32_t)(((lane >> 4) & 1) * 8 + (lane & 7));
    const uint32_t ldoff = (uint32_t)(((lane >> 3) & 1) * 16);
    const uint32_t lane_badd = lrow * 144u + ldoff;

    for (int t = blockIdx.x; t < NTILES; t += AGRID) {
        const int qb = t & 31;
        const int nh = t >> 5;
        const int n  = nh >> 2, h = nh & 3;

        const uint32_t* Qu = (const uint32_t*)(Q + (size_t)nh * L * DH
                                               + ((size_t)qb * BR + w * 16) * DH);
        const __half* Kg = K + (size_t)nh * L * DH;
        const __half* Vg = V + (size_t)nh * DH * L;

        uint32_t aq[4][4];
#pragma unroll
        for (int kc = 0; kc < 4; ++kc) {
            int b = g * 32 + 8 * kc + tig;
            aq[kc][0] = Qu[b];
            aq[kc][1] = Qu[b + 256];
            aq[kc][2] = Qu[b + 4];
            aq[kc][3] = Qu[b + 260];
        }

        float m0 = -1e30f, m1 = -1e30f, l0 = 0.f, l1 = 0.f;
        float acc[8][4] = {};

        auto stage = [&](int jb, int buf) {
            uint32_t kb = sbase + (uint32_t)buf * ABUF_B;
            uint32_t vb = kb + KTILE_H * 2;
            const __half* Ks = Kg + (size_t)jb * BC * DH;
            const __half* Vs = Vg + (size_t)jb * BC;
#pragma unroll
            for (int it = 0; it < 2; ++it) {
                int i = tid + it * 256;
                int j = i >> 3, dq = i & 7;
                cp16(kb + (uint32_t)(j * 144 + dq * 16), Ks + (size_t)j * DH + dq * 8);
            }
#pragma unroll
            for (int it = 0; it < 2; ++it) {
                int i = tid + it * 256;
                int j = i >> 3, dq = i & 7;
                cp16(vb + (uint32_t)(j * 144 + dq * 16), Vs + (size_t)j * L + dq * 8);
            }
        };

        stage(0, 0);
        cp_commit();

        for (int jb = 0; jb < NJB; ++jb) {
            if (jb + 1 < NJB) stage(jb + 1, (jb + 1) & 1);
            cp_commit();
            cp_wait1();
            __syncthreads();

            const uint32_t kbase = sbase + (uint32_t)(jb & 1) * ABUF_B;
            const uint32_t kaddr = kbase + lane_badd;
            const uint32_t vaddr = kbase + KTILE_H * 2 + lane_badd;

            // ---- S' = Q K^T (log2 domain) ----
            float c[8][4] = {};
#pragma unroll
            for (int kc = 0; kc < 4; ++kc) {
#pragma unroll
                for (int p = 0; p < 4; ++p) {
                    uint32_t b0a, b1a, b0b, b1b;
                    ldsm4(b0a, b1a, b0b, b1b, kaddr + (uint32_t)(p * 2304 + kc * 32));
                    mma_f16(c[2*p],   aq[kc][0], aq[kc][1], aq[kc][2], aq[kc][3], b0a, b1a);
                    mma_f16(c[2*p+1], aq[kc][0], aq[kc][1], aq[kc][2], aq[kc][3], b0b, b1b);
                }
            }

            float mx0 = -1e30f, mx1 = -1e30f;
#pragma unroll
            for (int nc = 0; nc < 8; ++nc) {
                mx0 = fmaxf(mx0, fmaxf(c[nc][0], c[nc][1]));
                mx1 = fmaxf(mx1, fmaxf(c[nc][2], c[nc][3]));
            }
            mx0 = fmaxf(mx0, __shfl_xor_sync(0xffffffffu, mx0, 1));
            mx0 = fmaxf(mx0, __shfl_xor_sync(0xffffffffu, mx0, 2));
            mx1 = fmaxf(mx1, __shfl_xor_sync(0xffffffffu, mx1, 1));
            mx1 = fmaxf(mx1, __shfl_xor_sync(0xffffffffu, mx1, 2));

            float mn0 = fmaxf(m0, mx0), mn1 = fmaxf(m1, mx1);
            float cr0 = ex2f(m0 - mn0), cr1 = ex2f(m1 - mn1);
            m0 = mn0; m1 = mn1;

            float ps0 = 0.f, ps1 = 0.f;
#pragma unroll
            for (int nc = 0; nc < 8; ++nc) {
                c[nc][0] = ex2f(c[nc][0] - mn0);
                c[nc][1] = ex2f(c[nc][1] - mn0);
                c[nc][2] = ex2f(c[nc][2] - mn1);
                c[nc][3] = ex2f(c[nc][3] - mn1);
                ps0 += c[nc][0] + c[nc][1];
                ps1 += c[nc][2] + c[nc][3];
            }
            ps0 += __shfl_xor_sync(0xffffffffu, ps0, 1);
            ps0 += __shfl_xor_sync(0xffffffffu, ps0, 2);
            ps1 += __shfl_xor_sync(0xffffffffu, ps1, 1);
            ps1 += __shfl_xor_sync(0xffffffffu, ps1, 2);
            l0 = l0 * cr0 + ps0;
            l1 = l1 * cr1 + ps1;

#pragma unroll
            for (int nc = 0; nc < 8; ++nc) {
                acc[nc][0] *= cr0; acc[nc][1] *= cr0;
                acc[nc][2] *= cr1; acc[nc][3] *= cr1;
            }

            uint32_t ph[8][2];
#pragma unroll
            for (int nc = 0; nc < 8; ++nc) {
                ph[nc][0] = packh2(c[nc][0], c[nc][1]);
                ph[nc][1] = packh2(c[nc][2], c[nc][3]);
            }

            // ---- O += P V ----
#pragma unroll
            for (int kc = 0; kc < 4; ++kc) {
                uint32_t a0 = ph[2 * kc][0];
                uint32_t a1 = ph[2 * kc][1];
                uint32_t a2 = ph[2 * kc + 1][0];
                uint32_t a3 = ph[2 * kc + 1][1];
#pragma unroll
                for (int p = 0; p < 4; ++p) {
                    uint32_t b0a, b1a, b0b, b1b;
                    ldsm4(b0a, b1a, b0b, b1b, vaddr + (uint32_t)(p * 2304 + kc * 32));
                    mma_f16(acc[2*p],   a0, a1, a2, a3, b0a, b1a);
                    mma_f16(acc[2*p+1], a0, a1, a2, a3, b0b, b1b);
                }
            }
            __syncthreads();
        }

        float il0 = 1.f / l0, il1 = 1.f / l1;
        int q0 = qb * BR + w * 16 + g;
        int q1 = q0 + 8;
        __half* aoB = AO + (size_t)n * C * L + (size_t)h * 64 * L;
#pragma unroll
        for (int nc = 0; nc < 8; ++nc) {
            int d0 = 8 * nc + 2 * tig;
            aoB[(size_t)d0 * L + q0]       = __float2half_rn(acc[nc][0] * il0);
            aoB[(size_t)(d0 + 1) * L + q0] = __float2half_rn(acc[nc][1] * il0);
            aoB[(size_t)d0 * L + q1]       = __float2half_rn(acc[nc][2] * il1);
            aoB[(size_t)(d0 + 1) * L + q1] = __float2half_rn(acc[nc][3] * il1);
        }
        __syncthreads();
    }
}

// ---------------- launch ----------------
extern "C" void kernel_launch(void* const* d_in, const int* in_sizes, int n_in,
                              void* d_out, int out_size) {
    const float* x     = (const float*)d_in[0];
    const float* gamma = (const float*)d_in[1];
    const float* beta  = (const float*)d_in[2];
    const float* Wq    = (const float*)d_in[3];
    const float* Wk    = (const float*)d_in[4];
    const float* Wv    = (const float*)d_in[5];
    const float* Wp    = (const float*)d_in[6];
    const float* bp    = (const float*)d_in[7];
    float* out = (float*)d_out;

    void *p_xn, *p_q, *p_k, *p_v, *p_ao, *p_wh, *p_st;
    cudaGetSymbolAddress(&p_xn, g_xnh);
    cudaGetSymbolAddress(&p_q,  g_qh);
    cudaGetSymbolAddress(&p_k,  g_kh);
    cudaGetSymbolAddress(&p_v,  g_vh);
    cudaGetSymbolAddress(&p_ao, g_aoh);
    cudaGetSymbolAddress(&p_wh, g_wh);
    cudaGetSymbolAddress(&p_st, g_st);
    const __half* wh = (const __half*)p_wh;

    wconv_kernel<<<dim3(C * C / (4 * 256), 4), 256>>>(Wq, Wk, Wv, Wp, (__half*)p_wh);
    gn_stats<<<NB * GROUPS, 256>>>(x, (float2*)p_st);
    gn_apply<<<(int)((size_t)NB * C * L / (256 * 8)), 256>>>(
        x, gamma, beta, (const float2*)p_st, (__half*)p_xn);

    cudaFuncSetAttribute(qkv_kernel, cudaFuncAttributeMaxDynamicSharedMemorySize, PROJ_SMEM);
    cudaFuncSetAttribute(projp_kernel, cudaFuncAttributeMaxDynamicSharedMemorySize, PROJ_SMEM);

    qkv_kernel<<<dim3(L / 128, 6, NB), 256, PROJ_SMEM>>>(
        wh, (const __half*)p_xn, (__half*)p_q, (__half*)p_k, (__half*)p_v);

    cudaFuncSetAttribute(attn_kernel, cudaFuncAttributeMaxDynamicSharedMemorySize, ATTN_SMEM);
    attn_kernel<<<AGRID, 256, ATTN_SMEM>>>(
        (const __half*)p_q, (const __half*)p_k, (const __half*)p_v, (__half*)p_ao);

    projp_kernel<<<dim3(L / 128, C / 128, NB), 256, PROJ_SMEM>>>(
        wh + 3 * C * C, (const __half*)p_ao, out, bp);
}